// round 13
// baseline (speedup 1.0000x reference)
#include <cuda_runtime.h>
#include <cuda_bf16.h>
#include <math.h>
#include <cstdint>

#define N_NODES 50000
#define N_EDGES 800000
#define C 96
#define GATE 288   // 3*C

#if defined(__CUDA_ARCH_FEAT_SM103_ALL) || defined(__CUDA_ARCH_FEAT_SM100_ALL)
#define TC_OK 1
#else
#define TC_OK 0
#endif

// ---- scratch (device globals; no allocations allowed) ----
__device__ float g_m  [N_NODES * C];
__device__ float g_agg[N_NODES * C];
__device__ float g_gi [N_NODES * GATE];
__device__ float g_gh [N_NODES * GATE];
__device__ float g_x1 [N_NODES * C];
__device__ float g_x2 [N_NODES * C];
__device__ uint32_t g_wimg [2][36864];   // gates W images (hi|lo)
__device__ uint32_t g_wximg[3][12288];   // per-layer x@W images (hi|lo)
// CSR
__device__ int g_deg [N_NODES];
__device__ int g_fill[N_NODES];
__device__ int g_off [N_NODES + 1];
__device__ int g_csr [N_EDGES];
__device__ int g_bsum[256];

// ============================================================
// PTX helpers
// ============================================================
__device__ __forceinline__ uint32_t smem_to_u32(const void* p) {
    uint32_t a;
    asm("{ .reg .u64 t; cvta.to.shared.u64 t, %1; cvt.u32.u64 %0, t; }" : "=r"(a) : "l"(p));
    return a;
}

#if TC_OK
__device__ __forceinline__ uint32_t elect_one_pred() {
    uint32_t pred;
    asm volatile("{\n\t.reg .pred p;\n\telect.sync _|p, 0xFFFFFFFF;\n\tselp.b32 %0, 1, 0, p;\n\t}" : "=r"(pred));
    return pred;
}
#define TCGEN05_ALLOC(smem_addr, nCols) \
    asm volatile("tcgen05.alloc.cta_group::1.sync.aligned.shared::cta.b32 [%0], %1;" \
        :: "r"((uint32_t)(smem_addr)), "r"((uint32_t)(nCols)) : "memory")
#define TCGEN05_DEALLOC(tmem, nCols) \
    asm volatile("tcgen05.dealloc.cta_group::1.sync.aligned.b32 %0, %1;" :: "r"(tmem), "r"((uint32_t)(nCols)))
#define TCGEN05_RELINQUISH() \
    asm volatile("tcgen05.relinquish_alloc_permit.cta_group::1.sync.aligned;")
#define TCGEN05_COMMIT(mbar) \
    asm volatile("tcgen05.commit.cta_group::1.mbarrier::arrive::one.shared::cluster.b64 [%0];" \
        :: "r"((uint32_t)(mbar)) : "memory")
#define TCGEN05_WAIT_LD() asm volatile("tcgen05.wait::ld.sync.aligned;" ::: "memory")
#define TCGEN05_FENCE_AFTER() asm volatile("tcgen05.fence::after_thread_sync;" ::: "memory")
#define FENCE_PROXY_ASYNC() asm volatile("fence.proxy.async.shared::cta;" ::: "memory")
#define MBARRIER_INIT(mbar, cnt) \
    asm volatile("mbarrier.init.shared.b64 [%0], %1;" :: "r"((uint32_t)(mbar)), "r"((uint32_t)(cnt)) : "memory")
#define MBARRIER_WAIT_PARITY(mbar, parity) do { \
    uint32_t _m = (uint32_t)(mbar); uint32_t _p = (uint32_t)(parity); uint32_t _d; \
    asm volatile("{\n\t.reg .pred p;\n\tmbarrier.try_wait.parity.acquire.cta.shared::cta.b64 p, [%1], %2;\n\tselp.b32 %0, 1, 0, p;\n\t}" \
        : "=r"(_d) : "r"(_m), "r"(_p) : "memory"); \
    if (!_d) { \
        asm volatile("{\n\t.reg .pred P1;\n\tWL_%=:\n\tmbarrier.try_wait.parity.acquire.cta.shared::cta.b64 P1, [%0], %1, 0x989680;\n\t@P1 bra.uni WD_%=;\n\tbra.uni WL_%=;\n\tWD_%=:\n\t}" \
            :: "r"(_m), "r"(_p) : "memory"); \
    } } while (0)
#define TCGEN05_LD_32X32B_X32(r, tmem_addr) \
    asm volatile( \
        "tcgen05.ld.sync.aligned.32x32b.x32.b32 " \
        "{%0, %1, %2, %3, %4, %5, %6, %7, " \
        " %8, %9, %10, %11, %12, %13, %14, %15, " \
        " %16, %17, %18, %19, %20, %21, %22, %23, " \
        " %24, %25, %26, %27, %28, %29, %30, %31}, [%32];" \
        : "=r"((r)[0]),  "=r"((r)[1]),  "=r"((r)[2]),  "=r"((r)[3]), \
          "=r"((r)[4]),  "=r"((r)[5]),  "=r"((r)[6]),  "=r"((r)[7]), \
          "=r"((r)[8]),  "=r"((r)[9]),  "=r"((r)[10]), "=r"((r)[11]), \
          "=r"((r)[12]), "=r"((r)[13]), "=r"((r)[14]), "=r"((r)[15]), \
          "=r"((r)[16]), "=r"((r)[17]), "=r"((r)[18]), "=r"((r)[19]), \
          "=r"((r)[20]), "=r"((r)[21]), "=r"((r)[22]), "=r"((r)[23]), \
          "=r"((r)[24]), "=r"((r)[25]), "=r"((r)[26]), "=r"((r)[27]), \
          "=r"((r)[28]), "=r"((r)[29]), "=r"((r)[30]), "=r"((r)[31]) \
        : "r"(tmem_addr))

__device__ __forceinline__ void mma_f16_ss(uint32_t d, uint64_t ad, uint64_t bd,
                                           uint32_t idesc, bool accum) {
    uint32_t en = accum ? 1u : 0u;
    uint32_t z = 0;
    asm volatile(
        "{\n\t.reg .pred p;\n\tsetp.ne.u32 p, %5, 0;\n\t"
        "tcgen05.mma.cta_group::1.kind::f16 [%0], %1, %2, %3, {%4, %4, %4, %4}, p;\n\t}"
        :: "r"(d), "l"(ad), "l"(bd), "r"(idesc), "r"(z), "r"(en) : "memory");
}
#endif // TC_OK

static constexpr uint64_t SMEM_DESC_BASE_SW128 =
    (uint64_t(2)  << 61) | (uint64_t(1) << 46) | (uint64_t(64) << 32) | (uint64_t(1) << 16);
#define MAKE_SMEM_DESC(base_addr) (SMEM_DESC_BASE_SW128 | ((uint64_t)((base_addr) >> 4) & 0x3FFF))
#define SMEM_SWIZZLE_128B(b) ((b) ^ (((b) >> 3) & 0x70))

__device__ __forceinline__ uint32_t pack2bf16(__nv_bfloat16 a, __nv_bfloat16 b) {
    __nv_bfloat162 t = __halves2bfloat162(a, b);
    return *reinterpret_cast<uint32_t*>(&t);
}

// ============================================================
// CSR build
// ============================================================
__global__ void csr_zero_kernel(int nrows)
{
    int t = blockIdx.x * blockDim.x + threadIdx.x;
    if (t < nrows) { g_deg[t] = 0; g_fill[t] = 0; }
}

__global__ void csr_count_kernel(const int* __restrict__ ei, int nedges)
{
    int t = blockIdx.x * blockDim.x + threadIdx.x;
    if (t < nedges) atomicAdd(&g_deg[ei[nedges + t]], 1);
}

__global__ void scan1_kernel(int nrows)
{
    __shared__ int s[256];
    const int t = threadIdx.x;
    int idx = blockIdx.x * 256 + t;
    int d = (idx < nrows) ? g_deg[idx] : 0;
    s[t] = d;
    __syncthreads();
#pragma unroll
    for (int o = 1; o < 256; o <<= 1) {
        int v = (t >= o) ? s[t - o] : 0;
        __syncthreads();
        s[t] += v;
        __syncthreads();
    }
    if (idx < nrows) g_off[idx] = s[t] - d;
    if (t == 255) g_bsum[blockIdx.x] = s[255];
}

__global__ void scan2_kernel(int nblocks, int nrows)
{
    __shared__ int s[256];
    const int t = threadIdx.x;
    int b = (t < nblocks) ? g_bsum[t] : 0;
    s[t] = b;
    __syncthreads();
#pragma unroll
    for (int o = 1; o < 256; o <<= 1) {
        int v = (t >= o) ? s[t - o] : 0;
        __syncthreads();
        s[t] += v;
        __syncthreads();
    }
    if (t < nblocks) g_bsum[t] = s[t] - b;
    if (t == 255) g_off[nrows] = s[255];
}

__global__ void scan3_kernel(int nrows)
{
    int idx = blockIdx.x * 256 + threadIdx.x;
    if (idx < nrows) g_off[idx] += g_bsum[blockIdx.x];
}

__global__ void csr_fill_kernel(const int* __restrict__ ei, int nedges)
{
    int t = blockIdx.x * blockDim.x + threadIdx.x;
    if (t >= nedges) return;
    int dst = ei[nedges + t];
    int pos = g_off[dst] + atomicAdd(&g_fill[dst], 1);
    g_csr[pos] = ei[t];
}

// ============================================================
// Aggregation: one warp per dst row; lanes 0-23 accumulate float4.
// ============================================================
__global__ void agg_kernel(const float* __restrict__ m,
                           float* __restrict__ agg, int nrows)
{
    int w    = (blockIdx.x * blockDim.x + threadIdx.x) >> 5;
    int lane = threadIdx.x & 31;
    if (w >= nrows || lane >= 24) return;

    const int beg = g_off[w];
    const int end = g_off[w + 1];
    const float4* m4 = (const float4*)m;

    float4 acc = make_float4(0.f, 0.f, 0.f, 0.f);
    int e = beg;
    for (; e + 1 < end; e += 2) {
        int s0 = g_csr[e];
        int s1 = g_csr[e + 1];
        float4 v0 = m4[s0 * 24 + lane];
        float4 v1 = m4[s1 * 24 + lane];
        acc.x += v0.x + v1.x;
        acc.y += v0.y + v1.y;
        acc.z += v0.z + v1.z;
        acc.w += v0.w + v1.w;
    }
    if (e < end) {
        float4 v = m4[g_csr[e] * 24 + lane];
        acc.x += v.x; acc.y += v.y; acc.z += v.z; acc.w += v.w;
    }
    ((float4*)agg)[w * 24 + lane] = acc;
}

// ============================================================
// Precompute swizzled bf16 hi/lo weight images
// ============================================================
__global__ void conv_w_kernel(const float* __restrict__ w_ih,
                              const float* __restrict__ w_hh)
{
    int tid = blockIdx.x * blockDim.x + threadIdx.x;
    if (tid >= 2 * 288 * 64) return;
    int tsr = tid / (288 * 64);
    int rem = tid - tsr * (288 * 64);
    int n  = rem >> 6;
    int k  = (rem & 63) * 2;
    const float* W = tsr ? w_hh : w_ih;

    float v0 = 0.f, v1 = 0.f;
    if (k < 96) { v0 = W[n * 96 + k]; v1 = W[n * 96 + k + 1]; }
    __nv_bfloat16 h0 = __float2bfloat16_rn(v0);
    __nv_bfloat16 h1 = __float2bfloat16_rn(v1);
    __nv_bfloat16 l0 = __float2bfloat16_rn(v0 - __bfloat162float(h0));
    __nv_bfloat16 l1 = __float2bfloat16_rn(v1 - __bfloat162float(h1));

    uint32_t byte_off = (uint32_t)(((n >> 3) + (k >> 6) * 36) * 1024
                                   + (n & 7) * 128 + (k & 63) * 2);
    uint32_t slot = SMEM_SWIZZLE_128B(byte_off) >> 2;
    g_wimg[tsr][slot]         = pack2bf16(h0, h1);
    g_wimg[tsr][slot + 18432] = pack2bf16(l0, l1);
}

__global__ void conv_wx_kernel(const float* __restrict__ weight)
{
    int tid = blockIdx.x * blockDim.x + threadIdx.x;
    if (tid >= 3 * 96 * 64) return;
    int l   = tid / (96 * 64);
    int rem = tid - l * (96 * 64);
    int n  = rem >> 6;
    int k  = (rem & 63) * 2;
    const float* W = weight + l * C * C;

    float v0 = 0.f, v1 = 0.f;
    if (k < 96) { v0 = W[k * 96 + n]; v1 = W[(k + 1) * 96 + n]; }
    __nv_bfloat16 h0 = __float2bfloat16_rn(v0);
    __nv_bfloat16 h1 = __float2bfloat16_rn(v1);
    __nv_bfloat16 l0 = __float2bfloat16_rn(v0 - __bfloat162float(h0));
    __nv_bfloat16 l1 = __float2bfloat16_rn(v1 - __bfloat162float(h1));

    uint32_t byte_off = (uint32_t)(((n >> 3) + (k >> 6) * 12) * 1024
                                   + (n & 7) * 128 + (k & 63) * 2);
    uint32_t slot = SMEM_SWIZZLE_128B(byte_off) >> 2;
    g_wximg[l][slot]        = pack2bf16(h0, h1);
    g_wximg[l][slot + 6144] = pack2bf16(l0, l1);
}

// ============================================================
// Pipelined MMA block shape: A double-buffered.
// smem: [0..16) tmem ptr + mbar, A buf0 @1024 (hi|lo 64KB),
//       A buf1 @66560, B hi @132096 (24KB), B lo @156672 (24KB).
// Total 181248 -> 1 CTA/SM (occupancy-2 shown not to matter; latency
// hiding comes from the in-block pipeline).
// ============================================================
#define PA(p)      (1024 + (p) * 65536)
#define PB_HI      132096
#define PB_LO      (PB_HI + 24576)
#define PIPE_TOTAL (PB_LO + 24576)     // 181248

#define TILES_PER_BLK 4

#if TC_OK
// Convert fp32 A tile -> hi/lo bf16 blocked atoms at smem+abase.
__device__ __forceinline__ void convert_A_tile(
    const float* __restrict__ A, int row0, int nrows, char* smem, int t,
    uint32_t abase)
{
    const float4* A4 = (const float4*)A;
#pragma unroll
    for (int i = 0; i < 12; i++) {
        int idx = t + i * 256;
        int r = idx / 24, q = idx - r * 24;
        int k0 = q * 4;
        int grow = row0 + r;
        float4 v = make_float4(0.f, 0.f, 0.f, 0.f);
        if (grow < nrows) v = A4[grow * 24 + q];

        __nv_bfloat16 hx = __float2bfloat16_rn(v.x);
        __nv_bfloat16 hy = __float2bfloat16_rn(v.y);
        __nv_bfloat16 hz = __float2bfloat16_rn(v.z);
        __nv_bfloat16 hw = __float2bfloat16_rn(v.w);
        __nv_bfloat16 lx = __float2bfloat16_rn(v.x - __bfloat162float(hx));
        __nv_bfloat16 ly = __float2bfloat16_rn(v.y - __bfloat162float(hy));
        __nv_bfloat16 lz = __float2bfloat16_rn(v.z - __bfloat162float(hz));
        __nv_bfloat16 lw = __float2bfloat16_rn(v.w - __bfloat162float(hw));

        uint32_t byte_off = (uint32_t)(((r >> 3) + (k0 >> 6) * 16) * 1024
                                       + (r & 7) * 128 + (k0 & 63) * 2);
        uint32_t sw = SMEM_SWIZZLE_128B(byte_off);
        *(uint2*)(smem + abase + sw)         = make_uint2(pack2bf16(hx, hy), pack2bf16(hz, hw));
        *(uint2*)(smem + abase + 32768 + sw) = make_uint2(pack2bf16(lx, ly), pack2bf16(lz, lw));
    }
}

// Issue 2 N-chunk x 3-pass x 6-Kstep MMA chain (A at abase, B at PB_*) -> D
// at dbase; commit to mbar. Caller: single elected thread of warp 0.
__device__ __forceinline__ void issue_mma_96(uint32_t smem_base, uint32_t abase,
                                             uint32_t dbase, uint32_t mbar)
{
    const uint32_t a_reg[3] = { abase, abase + 32768u, abase };
    const uint32_t b_reg[3] = { PB_HI, PB_HI, PB_LO };
#pragma unroll
    for (int c = 0; c < 2; c++) {
        const uint32_t n0 = (uint32_t)c * 64;
        const uint32_t nn = (c == 0) ? 64u : 32u;
        const uint32_t idesc = (1u << 4) | (1u << 7) | (1u << 10)
                             | ((nn / 8u) << 17) | (8u << 24);
        bool first = true;
#pragma unroll
        for (int p = 0; p < 3; p++) {
#pragma unroll
            for (int j = 0; j < 6; j++) {
                uint32_t a_addr = smem_base + a_reg[p]
                                + (uint32_t)((j >> 2) * 16384 + (j & 3) * 32);
                uint32_t b_addr = smem_base + b_reg[p]
                                + (uint32_t)((j >> 2) * 12288 + (j & 3) * 32)
                                + n0 * 128u;
                mma_f16_ss(dbase + n0,
                           MAKE_SMEM_DESC(a_addr), MAKE_SMEM_DESC(b_addr),
                           idesc, !first);
                first = false;
            }
        }
    }
    TCGEN05_COMMIT(mbar);
}
#endif // TC_OK

// ============================================================
// x@W via tcgen05: pipelined 4-tile blocks, A double-buffered.
// ============================================================
__global__ void __launch_bounds__(256) xw_mma_kernel(
    const uint32_t* __restrict__ Bimg, const float* __restrict__ X,
    const float* __restrict__ Wfb, float* __restrict__ M, int nrows)
{
    extern __shared__ char smem[];
    const int t = threadIdx.x;

    const int ntiles = (nrows + 127) >> 7;
    const int tile0  = blockIdx.x * TILES_PER_BLK;
    int nact = ntiles - tile0;
    if (nact <= 0) return;
    if (nact > TILES_PER_BLK) nact = TILES_PER_BLK;

#if TC_OK
    const uint32_t smem_base = smem_to_u32(smem);
    const int wid  = t >> 5;
    const int lane = t & 31;

    if (wid == 0) {
        TCGEN05_ALLOC(smem_base, 256);
        TCGEN05_RELINQUISH();
    }
    if (t == 0) MBARRIER_INIT(smem_base + 8, 1);

    // B: copy layer image once (hi+lo contiguous, 3072 uint4)
    {
        const uint4* src = (const uint4*)Bimg;
        uint4* dst = (uint4*)(smem + PB_HI);
#pragma unroll
        for (int i = 0; i < 12; i++) dst[t + i * 256] = src[t + i * 256];
    }

    __syncthreads();
    uint32_t tmem_base;
    asm volatile("ld.shared.b32 %0, [%1];" : "=r"(tmem_base) : "r"(smem_base));

    for (int it = 0; it < nact; it++) {
        const int row0 = (tile0 + it) * 128;

        // convert into buf(it&1); safe: last reader was MMA(it-2), waited below
        convert_A_tile(X, row0, nrows, smem, t, PA(it & 1));
        FENCE_PROXY_ASYNC();
        __syncthreads();

        if (it > 0) {
            MBARRIER_WAIT_PARITY(smem_base + 8, (it - 1) & 1);
            TCGEN05_FENCE_AFTER();
        }

        if (wid == 0) {
            TCGEN05_FENCE_AFTER();
            if (elect_one_pred())
                issue_mma_96(smem_base, PA(it & 1),
                             tmem_base + (uint32_t)(it & 1) * 128, smem_base + 8);
        }

        // epilogue of previous tile overlaps MMA(it)
        if (it > 0) {
            const int prow0 = (tile0 + it - 1) * 128;
            const uint32_t dbase = tmem_base + (uint32_t)((it - 1) & 1) * 128;
            const int sub = wid & 3;
            const int row = prow0 + sub * 32 + lane;
            const int nch = (wid < 4) ? 2 : 1;
            const int cst = (wid < 4) ? 0 : 64;
            for (int ch = 0; ch < nch; ch++) {
                int c0 = cst + ch * 32;
                uint32_t d[32];
                TCGEN05_LD_32X32B_X32(d, dbase + c0);
                TCGEN05_WAIT_LD();
                if (row < nrows) {
                    float4* op = (float4*)(M + (size_t)row * C + c0);
#pragma unroll
                    for (int i = 0; i < 8; i++) {
                        float4 v;
                        v.x = __uint_as_float(d[4 * i + 0]);
                        v.y = __uint_as_float(d[4 * i + 1]);
                        v.z = __uint_as_float(d[4 * i + 2]);
                        v.w = __uint_as_float(d[4 * i + 3]);
                        op[i] = v;
                    }
                }
            }
        }
        __syncthreads();
    }

    // final tile epilogue
    MBARRIER_WAIT_PARITY(smem_base + 8, (nact - 1) & 1);
    TCGEN05_FENCE_AFTER();
    {
        const int prow0 = (tile0 + nact - 1) * 128;
        const uint32_t dbase = tmem_base + (uint32_t)((nact - 1) & 1) * 128;
        const int sub = wid & 3;
        const int row = prow0 + sub * 32 + lane;
        const int nch = (wid < 4) ? 2 : 1;
        const int cst = (wid < 4) ? 0 : 64;
        for (int ch = 0; ch < nch; ch++) {
            int c0 = cst + ch * 32;
            uint32_t d[32];
            TCGEN05_LD_32X32B_X32(d, dbase + c0);
            TCGEN05_WAIT_LD();
            if (row < nrows) {
                float4* op = (float4*)(M + (size_t)row * C + c0);
#pragma unroll
                for (int i = 0; i < 8; i++) {
                    float4 v;
                    v.x = __uint_as_float(d[4 * i + 0]);
                    v.y = __uint_as_float(d[4 * i + 1]);
                    v.z = __uint_as_float(d[4 * i + 2]);
                    v.w = __uint_as_float(d[4 * i + 3]);
                    op[i] = v;
                }
            }
        }
    }

    __syncthreads();
    if (wid == 0) {
        TCGEN05_DEALLOC(tmem_base, 256);
    }
#else
    // SIMT fallback (never runs on HW)
    for (int it = 0; it < nact; it++) {
        int row0 = (tile0 + it) * 128;
        for (int idx = t; idx < 128 * 96; idx += 256) {
            int r = idx / 96, c = idx - r * 96;
            int gr = row0 + r;
            if (gr < nrows) {
                float s = 0.f;
                for (int k = 0; k < 96; k++) s = fmaf(X[gr * 96 + k], Wfb[k * 96 + c], s);
                M[(size_t)gr * C + c] = s;
            }
        }
    }
#endif
}

// ============================================================
// Gates GEMM: pipelined 4-tile blocks, A double-buffered.
// grid ((ntiles+3)/4, 6); y&1 -> gi/gh, y>>1 -> N-third h.
// ============================================================
__global__ void __launch_bounds__(256) gates_mma_kernel(
    const float* __restrict__ A0, const float* __restrict__ A1,
    const float* __restrict__ bias0, const float* __restrict__ bias1,
    float* __restrict__ O0, float* __restrict__ O1, int nrows)
{
    extern __shared__ char smem[];
    const int t = threadIdx.x;
    const int y = blockIdx.y & 1;
    const int h = blockIdx.y >> 1;             // gate cols [96h, 96h+96)

    const float* A    = y ? A1 : A0;
    const float* bias = y ? bias1 : bias0;
    float*       O    = y ? O1 : O0;

    const int ntiles = (nrows + 127) >> 7;
    const int tile0  = blockIdx.x * TILES_PER_BLK;
    int nact = ntiles - tile0;
    if (nact <= 0) return;
    if (nact > TILES_PER_BLK) nact = TILES_PER_BLK;

#if TC_OK
    const uint32_t smem_base = smem_to_u32(smem);
    const int wid  = t >> 5;
    const int lane = t & 31;

    if (wid == 0) {
        TCGEN05_ALLOC(smem_base, 256);
        TCGEN05_RELINQUISH();
    }
    if (t == 0) MBARRIER_INIT(smem_base + 8, 1);

    // B: copy 96-row slice of the W image (once per block)
    {
        const uint4* src = (const uint4*)(g_wimg[y]);
        uint4* dsth = (uint4*)(smem + PB_HI);
        uint4* dstl = (uint4*)(smem + PB_LO);
        const int b0 = (12 * h) * 64;
        const int b1 = (36 + 12 * h) * 64;
#pragma unroll
        for (int i = 0; i < 3; i++) {
            int o = t + i * 256;
            dsth[o]        = src[b0 + o];
            dsth[768 + o]  = src[b1 + o];
            dstl[o]        = src[4608 + b0 + o];
            dstl[768 + o]  = src[4608 + b1 + o];
        }
    }

    __syncthreads();
    uint32_t tmem_base;
    asm volatile("ld.shared.b32 %0, [%1];" : "=r"(tmem_base) : "r"(smem_base));

    const float4* b4 = (const float4*)bias;

    for (int it = 0; it < nact; it++) {
        const int row0 = (tile0 + it) * 128;

        convert_A_tile(A, row0, nrows, smem, t, PA(it & 1));
        FENCE_PROXY_ASYNC();
        __syncthreads();

        if (it > 0) {
            MBARRIER_WAIT_PARITY(smem_base + 8, (it - 1) & 1);
            TCGEN05_FENCE_AFTER();
        }

        if (wid == 0) {
            TCGEN05_FENCE_AFTER();
            if (elect_one_pred())
                issue_mma_96(smem_base, PA(it & 1),
                             tmem_base + (uint32_t)(it & 1) * 128, smem_base + 8);
        }

        // epilogue of previous tile overlaps MMA(it)
        if (it > 0) {
            const int prow0 = (tile0 + it - 1) * 128;
            const uint32_t dbase = tmem_base + (uint32_t)((it - 1) & 1) * 128;
            const int sub = wid & 3;
            const int row = prow0 + sub * 32 + lane;
            const int nch = (wid < 4) ? 2 : 1;
            const int cst = (wid < 4) ? 0 : 64;
            for (int ch = 0; ch < nch; ch++) {
                int c0 = cst + ch * 32;
                uint32_t d[32];
                TCGEN05_LD_32X32B_X32(d, dbase + c0);
                TCGEN05_WAIT_LD();
                if (row < nrows) {
                    int gc = h * 96 + c0;
                    float4* op = (float4*)(O + (size_t)row * GATE + gc);
#pragma unroll
                    for (int i = 0; i < 8; i++) {
                        float4 bb = __ldg(&b4[gc / 4 + i]);
                        float4 v;
                        v.x = __uint_as_float(d[4 * i + 0]) + bb.x;
                        v.y = __uint_as_float(d[4 * i + 1]) + bb.y;
                        v.z = __uint_as_float(d[4 * i + 2]) + bb.z;
                        v.w = __uint_as_float(d[4 * i + 3]) + bb.w;
                        op[i] = v;
                    }
                }
            }
        }
        __syncthreads();
    }

    // final tile epilogue
    MBARRIER_WAIT_PARITY(smem_base + 8, (nact - 1) & 1);
    TCGEN05_FENCE_AFTER();
    {
        const int prow0 = (tile0 + nact - 1) * 128;
        const uint32_t dbase = tmem_base + (uint32_t)((nact - 1) & 1) * 128;
        const int sub = wid & 3;
        const int row = prow0 + sub * 32 + lane;
        const int nch = (wid < 4) ? 2 : 1;
        const int cst = (wid < 4) ? 0 : 64;
        for (int ch = 0; ch < nch; ch++) {
            int c0 = cst + ch * 32;
            uint32_t d[32];
            TCGEN05_LD_32X32B_X32(d, dbase + c0);
            TCGEN05_WAIT_LD();
            if (row < nrows) {
                int gc = h * 96 + c0;
                float4* op = (float4*)(O + (size_t)row * GATE + gc);
#pragma unroll
                for (int i = 0; i < 8; i++) {
                    float4 bb = __ldg(&b4[gc / 4 + i]);
                    float4 v;
                    v.x = __uint_as_float(d[4 * i + 0]) + bb.x;
                    v.y = __uint_as_float(d[4 * i + 1]) + bb.y;
                    v.z = __uint_as_float(d[4 * i + 2]) + bb.z;
                    v.w = __uint_as_float(d[4 * i + 3]) + bb.w;
                    op[i] = v;
                }
            }
        }
    }

    __syncthreads();
    if (wid == 0) {
        TCGEN05_DEALLOC(tmem_base, 256);
    }
#else
    // SIMT fallback (never runs on HW)
    for (int it = 0; it < nact; it++) {
        int row0 = (tile0 + it) * 128;
        for (int idx = t; idx < 128 * 96; idx += 256) {
            int r = idx / 96, cl = idx - r * 96;
            int c = h * 96 + cl;
            int gr = row0 + r;
            if (gr < nrows) {
                float s = bias[c];
                for (int k = 0; k < 96; k++) {
                    uint32_t byte_off = (uint32_t)(((c >> 3) + (k >> 6) * 36) * 1024
                                                   + (c & 7) * 128 + (k & 63) * 2);
                    uint32_t slot = SMEM_SWIZZLE_128B(byte_off & ~3u) >> 2;
                    uint32_t hv = g_wimg[y][slot];
                    uint32_t lv = g_wimg[y][slot + 18432];
                    int sh = (k & 1) ? 16 : 0;
                    float wh = __bfloat162float(__ushort_as_bfloat16((unsigned short)(hv >> sh)));
                    float wl = __bfloat162float(__ushort_as_bfloat16((unsigned short)(lv >> sh)));
                    s = fmaf(A[gr * 96 + k], wh + wl, s);
                }
                O[(size_t)gr * GATE + c] = s;
            }
        }
    }
#endif
}

// ============================================================
// GRU elementwise
// ============================================================
__device__ __forceinline__ float gru_one(float ir, float iz, float inn,
                                         float hr, float hz, float hn, float h)
{
    float r = 1.f / (1.f + expf(-(ir + hr)));
    float z = 1.f / (1.f + expf(-(iz + hz)));
    float n = tanhf(inn + r * hn);
    return (1.f - z) * n + z * h;
}

__global__ void gru_kernel(const float* __restrict__ GI,
                           const float* __restrict__ GH,
                           const float* __restrict__ H,
                           float* __restrict__ OUT,
                           int nrows)
{
    int tid = blockIdx.x * blockDim.x + threadIdx.x;
    int total = nrows * 24;
    if (tid >= total) return;
    int n = tid / 24;
    int q = tid - n * 24;

    const float4* gi4 = (const float4*)GI;
    const float4* gh4 = (const float4*)GH;
    float4 ir  = gi4[n * 72 + q];
    float4 iz  = gi4[n * 72 + 24 + q];
    float4 inn = gi4[n * 72 + 48 + q];
    float4 hr  = gh4[n * 72 + q];
    float4 hz  = gh4[n * 72 + 24 + q];
    float4 hn  = gh4[n * 72 + 48 + q];
    float4 h   = ((const float4*)H)[n * 24 + q];

    float4 o;
    o.x = gru_one(ir.x, iz.x, inn.x, hr.x, hz.x, hn.x, h.x);
    o.y = gru_one(ir.y, iz.y, inn.y, hr.y, hz.y, hn.y, h.y);
    o.z = gru_one(ir.z, iz.z, inn.z, hr.z, hz.z, hn.z, h.z);
    o.w = gru_one(ir.w, iz.w, inn.w, hr.w, hz.w, hn.w, h.w);

    ((float4*)OUT)[n * 24 + q] = o;
}

// ============================================================
extern "C" void kernel_launch(void* const* d_in, const int* in_sizes, int n_in,
                              void* d_out, int out_size)
{
    const float* x      = (const float*)d_in[0];
    const int*   ei     = (const int*)  d_in[1];
    const float* weight = (const float*)d_in[2];
    const float* w_ih   = (const float*)d_in[3];
    const float* w_hh   = (const float*)d_in[4];
    const float* b_ih   = (const float*)d_in[5];
    const float* b_hh   = (const float*)d_in[6];
    float* out = (float*)d_out;

    const int nrows  = in_sizes[0] / C;
    const int nedges = in_sizes[1] / 2;

    float *pm, *pagg, *pgi, *pgh, *px1, *px2;
    uint32_t* pwx;
    cudaGetSymbolAddress((void**)&pm,   g_m);
    cudaGetSymbolAddress((void**)&pagg, g_agg);
    cudaGetSymbolAddress((void**)&pgi,  g_gi);
    cudaGetSymbolAddress((void**)&pgh,  g_gh);
    cudaGetSymbolAddress((void**)&px1,  g_x1);
    cudaGetSymbolAddress((void**)&px2,  g_x2);
    cudaGetSymbolAddress((void**)&pwx,  g_wximg);

    cudaFuncSetAttribute(xw_mma_kernel,    cudaFuncAttributeMaxDynamicSharedMemorySize, PIPE_TOTAL);
    cudaFuncSetAttribute(gates_mma_kernel, cudaFuncAttributeMaxDynamicSharedMemorySize, PIPE_TOTAL);

    const int rblocks128 = (nrows + 127) / 128;
    const int pblocks    = (rblocks128 + TILES_PER_BLK - 1) / TILES_PER_BLK;
    dim3 g_gates(pblocks, 6);
    const int gru_blocks = (nrows * 24 + 255) / 256;
    const int agg_blocks = (nrows * 32 + 255) / 256;
    const int nb256      = (nrows + 255) / 256;

    // Precompute: W images + CSR (layer-invariant)
    conv_w_kernel<<<(2 * 288 * 64 + 255) / 256, 256>>>(w_ih, w_hh);
    conv_wx_kernel<<<(3 * 96 * 64 + 255) / 256, 256>>>(weight);
    csr_zero_kernel<<<nb256, 256>>>(nrows);
    csr_count_kernel<<<(nedges + 255) / 256, 256>>>(ei, nedges);
    scan1_kernel<<<nb256, 256>>>(nrows);
    scan2_kernel<<<1, 256>>>(nb256, nrows);
    scan3_kernel<<<nb256, 256>>>(nrows);
    csr_fill_kernel<<<(nedges + 255) / 256, 256>>>(ei, nedges);

    const float* xin = x;
    float* xbufs[3] = {px1, px2, out};

    for (int l = 0; l < 3; l++) {
        float* xout = xbufs[l];
        xw_mma_kernel<<<pblocks, 256, PIPE_TOTAL>>>(pwx + l * 12288, xin,
                                                    weight + l * C * C, pm, nrows);
        agg_kernel<<<agg_blocks, 256>>>(pm, pagg, nrows);
        gates_mma_kernel<<<g_gates, 256, PIPE_TOTAL>>>(pagg, xin, b_ih, b_hh,
                                                       pgi, pgh, nrows);
        gru_kernel<<<gru_blocks, 256>>>(pgi, pgh, xin, xout, nrows);
        xin = xout;
    }
}

// round 14
// speedup vs baseline: 1.0825x; 1.0825x over previous
#include <cuda_runtime.h>
#include <cuda_bf16.h>
#include <math.h>
#include <cstdint>

#define N_NODES 50000
#define N_EDGES 800000
#define C 96
#define GATE 288   // 3*C

#if defined(__CUDA_ARCH_FEAT_SM103_ALL) || defined(__CUDA_ARCH_FEAT_SM100_ALL)
#define TC_OK 1
#else
#define TC_OK 0
#endif

// ---- scratch (device globals; no allocations allowed) ----
__device__ float g_m  [N_NODES * C];
__device__ float g_agg[N_NODES * C];
__device__ float g_gi [N_NODES * GATE];
__device__ float g_gh [N_NODES * GATE];
__device__ float g_x1 [N_NODES * C];
__device__ float g_x2 [N_NODES * C];
__device__ uint32_t g_wimg [2][36864];   // gates W images (hi|lo)
__device__ uint32_t g_wximg[3][12288];   // per-layer x@W images (hi|lo)
// CSR
__device__ int g_deg [N_NODES];
__device__ int g_fill[N_NODES];
__device__ int g_off [N_NODES + 1];
__device__ int g_csr [N_EDGES];
__device__ int g_bsum[256];

// ============================================================
// PTX helpers
// ============================================================
__device__ __forceinline__ uint32_t smem_to_u32(const void* p) {
    uint32_t a;
    asm("{ .reg .u64 t; cvta.to.shared.u64 t, %1; cvt.u32.u64 %0, t; }" : "=r"(a) : "l"(p));
    return a;
}

#if TC_OK
__device__ __forceinline__ uint32_t elect_one_pred() {
    uint32_t pred;
    asm volatile("{\n\t.reg .pred p;\n\telect.sync _|p, 0xFFFFFFFF;\n\tselp.b32 %0, 1, 0, p;\n\t}" : "=r"(pred));
    return pred;
}
#define TCGEN05_ALLOC(smem_addr, nCols) \
    asm volatile("tcgen05.alloc.cta_group::1.sync.aligned.shared::cta.b32 [%0], %1;" \
        :: "r"((uint32_t)(smem_addr)), "r"((uint32_t)(nCols)) : "memory")
#define TCGEN05_DEALLOC(tmem, nCols) \
    asm volatile("tcgen05.dealloc.cta_group::1.sync.aligned.b32 %0, %1;" :: "r"(tmem), "r"((uint32_t)(nCols)))
#define TCGEN05_RELINQUISH() \
    asm volatile("tcgen05.relinquish_alloc_permit.cta_group::1.sync.aligned;")
#define TCGEN05_COMMIT(mbar) \
    asm volatile("tcgen05.commit.cta_group::1.mbarrier::arrive::one.shared::cluster.b64 [%0];" \
        :: "r"((uint32_t)(mbar)) : "memory")
#define TCGEN05_WAIT_LD() asm volatile("tcgen05.wait::ld.sync.aligned;" ::: "memory")
#define TCGEN05_FENCE_AFTER() asm volatile("tcgen05.fence::after_thread_sync;" ::: "memory")
#define FENCE_PROXY_ASYNC() asm volatile("fence.proxy.async.shared::cta;" ::: "memory")
#define MBARRIER_INIT(mbar, cnt) \
    asm volatile("mbarrier.init.shared.b64 [%0], %1;" :: "r"((uint32_t)(mbar)), "r"((uint32_t)(cnt)) : "memory")
#define MBARRIER_WAIT_PARITY(mbar, parity) do { \
    uint32_t _m = (uint32_t)(mbar); uint32_t _p = (uint32_t)(parity); uint32_t _d; \
    asm volatile("{\n\t.reg .pred p;\n\tmbarrier.try_wait.parity.acquire.cta.shared::cta.b64 p, [%1], %2;\n\tselp.b32 %0, 1, 0, p;\n\t}" \
        : "=r"(_d) : "r"(_m), "r"(_p) : "memory"); \
    if (!_d) { \
        asm volatile("{\n\t.reg .pred P1;\n\tWL_%=:\n\tmbarrier.try_wait.parity.acquire.cta.shared::cta.b64 P1, [%0], %1, 0x989680;\n\t@P1 bra.uni WD_%=;\n\tbra.uni WL_%=;\n\tWD_%=:\n\t}" \
            :: "r"(_m), "r"(_p) : "memory"); \
    } } while (0)
#define TCGEN05_LD_32X32B_X32(r, tmem_addr) \
    asm volatile( \
        "tcgen05.ld.sync.aligned.32x32b.x32.b32 " \
        "{%0, %1, %2, %3, %4, %5, %6, %7, " \
        " %8, %9, %10, %11, %12, %13, %14, %15, " \
        " %16, %17, %18, %19, %20, %21, %22, %23, " \
        " %24, %25, %26, %27, %28, %29, %30, %31}, [%32];" \
        : "=r"((r)[0]),  "=r"((r)[1]),  "=r"((r)[2]),  "=r"((r)[3]), \
          "=r"((r)[4]),  "=r"((r)[5]),  "=r"((r)[6]),  "=r"((r)[7]), \
          "=r"((r)[8]),  "=r"((r)[9]),  "=r"((r)[10]), "=r"((r)[11]), \
          "=r"((r)[12]), "=r"((r)[13]), "=r"((r)[14]), "=r"((r)[15]), \
          "=r"((r)[16]), "=r"((r)[17]), "=r"((r)[18]), "=r"((r)[19]), \
          "=r"((r)[20]), "=r"((r)[21]), "=r"((r)[22]), "=r"((r)[23]), \
          "=r"((r)[24]), "=r"((r)[25]), "=r"((r)[26]), "=r"((r)[27]), \
          "=r"((r)[28]), "=r"((r)[29]), "=r"((r)[30]), "=r"((r)[31]) \
        : "r"(tmem_addr))

__device__ __forceinline__ void mma_f16_ss(uint32_t d, uint64_t ad, uint64_t bd,
                                           uint32_t idesc, bool accum) {
    uint32_t en = accum ? 1u : 0u;
    uint32_t z = 0;
    asm volatile(
        "{\n\t.reg .pred p;\n\tsetp.ne.u32 p, %5, 0;\n\t"
        "tcgen05.mma.cta_group::1.kind::f16 [%0], %1, %2, %3, {%4, %4, %4, %4}, p;\n\t}"
        :: "r"(d), "l"(ad), "l"(bd), "r"(idesc), "r"(z), "r"(en) : "memory");
}
#endif // TC_OK

static constexpr uint64_t SMEM_DESC_BASE_SW128 =
    (uint64_t(2)  << 61) | (uint64_t(1) << 46) | (uint64_t(64) << 32) | (uint64_t(1) << 16);
#define MAKE_SMEM_DESC(base_addr) (SMEM_DESC_BASE_SW128 | ((uint64_t)((base_addr) >> 4) & 0x3FFF))
#define SMEM_SWIZZLE_128B(b) ((b) ^ (((b) >> 3) & 0x70))

__device__ __forceinline__ uint32_t pack2bf16(__nv_bfloat16 a, __nv_bfloat16 b) {
    __nv_bfloat162 t = __halves2bfloat162(a, b);
    return *reinterpret_cast<uint32_t*>(&t);
}

// ============================================================
// CSR build
// ============================================================
__global__ void csr_zero_kernel(int nrows)
{
    int t = blockIdx.x * blockDim.x + threadIdx.x;
    if (t < nrows) { g_deg[t] = 0; g_fill[t] = 0; }
}

__global__ void csr_count_kernel(const int* __restrict__ ei, int nedges)
{
    int t = blockIdx.x * blockDim.x + threadIdx.x;
    if (t < nedges) atomicAdd(&g_deg[ei[nedges + t]], 1);
}

__global__ void scan1_kernel(int nrows)
{
    __shared__ int s[256];
    const int t = threadIdx.x;
    int idx = blockIdx.x * 256 + t;
    int d = (idx < nrows) ? g_deg[idx] : 0;
    s[t] = d;
    __syncthreads();
#pragma unroll
    for (int o = 1; o < 256; o <<= 1) {
        int v = (t >= o) ? s[t - o] : 0;
        __syncthreads();
        s[t] += v;
        __syncthreads();
    }
    if (idx < nrows) g_off[idx] = s[t] - d;
    if (t == 255) g_bsum[blockIdx.x] = s[255];
}

__global__ void scan2_kernel(int nblocks, int nrows)
{
    __shared__ int s[256];
    const int t = threadIdx.x;
    int b = (t < nblocks) ? g_bsum[t] : 0;
    s[t] = b;
    __syncthreads();
#pragma unroll
    for (int o = 1; o < 256; o <<= 1) {
        int v = (t >= o) ? s[t - o] : 0;
        __syncthreads();
        s[t] += v;
        __syncthreads();
    }
    if (t < nblocks) g_bsum[t] = s[t] - b;
    if (t == 255) g_off[nrows] = s[255];
}

__global__ void scan3_kernel(int nrows)
{
    int idx = blockIdx.x * 256 + threadIdx.x;
    if (idx < nrows) g_off[idx] += g_bsum[blockIdx.x];
}

__global__ void csr_fill_kernel(const int* __restrict__ ei, int nedges)
{
    int t = blockIdx.x * blockDim.x + threadIdx.x;
    if (t >= nedges) return;
    int dst = ei[nedges + t];
    int pos = g_off[dst] + atomicAdd(&g_fill[dst], 1);
    g_csr[pos] = ei[t];
}

// ============================================================
// Aggregation: one warp per dst row; lanes 0-23 accumulate float4.
// ============================================================
__global__ void agg_kernel(const float* __restrict__ m,
                           float* __restrict__ agg, int nrows)
{
    int w    = (blockIdx.x * blockDim.x + threadIdx.x) >> 5;
    int lane = threadIdx.x & 31;
    if (w >= nrows || lane >= 24) return;

    const int beg = g_off[w];
    const int end = g_off[w + 1];
    const float4* m4 = (const float4*)m;

    float4 acc = make_float4(0.f, 0.f, 0.f, 0.f);
    int e = beg;
    for (; e + 1 < end; e += 2) {
        int s0 = g_csr[e];
        int s1 = g_csr[e + 1];
        float4 v0 = m4[s0 * 24 + lane];
        float4 v1 = m4[s1 * 24 + lane];
        acc.x += v0.x + v1.x;
        acc.y += v0.y + v1.y;
        acc.z += v0.z + v1.z;
        acc.w += v0.w + v1.w;
    }
    if (e < end) {
        float4 v = m4[g_csr[e] * 24 + lane];
        acc.x += v.x; acc.y += v.y; acc.z += v.z; acc.w += v.w;
    }
    ((float4*)agg)[w * 24 + lane] = acc;
}

// ============================================================
// Precompute swizzled bf16 hi/lo weight images
// ============================================================
__global__ void conv_w_kernel(const float* __restrict__ w_ih,
                              const float* __restrict__ w_hh)
{
    int tid = blockIdx.x * blockDim.x + threadIdx.x;
    if (tid >= 2 * 288 * 64) return;
    int tsr = tid / (288 * 64);
    int rem = tid - tsr * (288 * 64);
    int n  = rem >> 6;
    int k  = (rem & 63) * 2;
    const float* W = tsr ? w_hh : w_ih;

    float v0 = 0.f, v1 = 0.f;
    if (k < 96) { v0 = W[n * 96 + k]; v1 = W[n * 96 + k + 1]; }
    __nv_bfloat16 h0 = __float2bfloat16_rn(v0);
    __nv_bfloat16 h1 = __float2bfloat16_rn(v1);
    __nv_bfloat16 l0 = __float2bfloat16_rn(v0 - __bfloat162float(h0));
    __nv_bfloat16 l1 = __float2bfloat16_rn(v1 - __bfloat162float(h1));

    uint32_t byte_off = (uint32_t)(((n >> 3) + (k >> 6) * 36) * 1024
                                   + (n & 7) * 128 + (k & 63) * 2);
    uint32_t slot = SMEM_SWIZZLE_128B(byte_off) >> 2;
    g_wimg[tsr][slot]         = pack2bf16(h0, h1);
    g_wimg[tsr][slot + 18432] = pack2bf16(l0, l1);
}

__global__ void conv_wx_kernel(const float* __restrict__ weight)
{
    int tid = blockIdx.x * blockDim.x + threadIdx.x;
    if (tid >= 3 * 96 * 64) return;
    int l   = tid / (96 * 64);
    int rem = tid - l * (96 * 64);
    int n  = rem >> 6;
    int k  = (rem & 63) * 2;
    const float* W = weight + l * C * C;

    float v0 = 0.f, v1 = 0.f;
    if (k < 96) { v0 = W[k * 96 + n]; v1 = W[(k + 1) * 96 + n]; }
    __nv_bfloat16 h0 = __float2bfloat16_rn(v0);
    __nv_bfloat16 h1 = __float2bfloat16_rn(v1);
    __nv_bfloat16 l0 = __float2bfloat16_rn(v0 - __bfloat162float(h0));
    __nv_bfloat16 l1 = __float2bfloat16_rn(v1 - __bfloat162float(h1));

    uint32_t byte_off = (uint32_t)(((n >> 3) + (k >> 6) * 12) * 1024
                                   + (n & 7) * 128 + (k & 63) * 2);
    uint32_t slot = SMEM_SWIZZLE_128B(byte_off) >> 2;
    g_wximg[l][slot]        = pack2bf16(h0, h1);
    g_wximg[l][slot + 6144] = pack2bf16(l0, l1);
}

// ============================================================
// Shared 128x96-tile MMA block shape (smem 115712 -> 2 CTAs/SM)
// ============================================================
#define XW_AHI    1024
#define XW_ALO    (XW_AHI + 32768)     // 33792
#define XW_BHI    (XW_ALO + 32768)     // 66560
#define XW_BLO    (XW_BHI + 24576)     // 91136
#define XW_TOTAL  (XW_BLO + 24576)     // 115712

#define GATES_TILES 8
#define XW_TILES    2

#if TC_OK
// Convert fp32 A tile -> hi/lo bf16 blocked atoms in smem.
__device__ __forceinline__ void convert_A_tile(
    const float* __restrict__ A, int row0, int nrows, char* smem, int t)
{
    const float4* A4 = (const float4*)A;
#pragma unroll
    for (int i = 0; i < 12; i++) {
        int idx = t + i * 256;
        int r = idx / 24, q = idx - r * 24;
        int k0 = q * 4;
        int grow = row0 + r;
        float4 v = make_float4(0.f, 0.f, 0.f, 0.f);
        if (grow < nrows) v = A4[grow * 24 + q];

        __nv_bfloat16 hx = __float2bfloat16_rn(v.x);
        __nv_bfloat16 hy = __float2bfloat16_rn(v.y);
        __nv_bfloat16 hz = __float2bfloat16_rn(v.z);
        __nv_bfloat16 hw = __float2bfloat16_rn(v.w);
        __nv_bfloat16 lx = __float2bfloat16_rn(v.x - __bfloat162float(hx));
        __nv_bfloat16 ly = __float2bfloat16_rn(v.y - __bfloat162float(hy));
        __nv_bfloat16 lz = __float2bfloat16_rn(v.z - __bfloat162float(hz));
        __nv_bfloat16 lw = __float2bfloat16_rn(v.w - __bfloat162float(hw));

        uint32_t byte_off = (uint32_t)(((r >> 3) + (k0 >> 6) * 16) * 1024
                                       + (r & 7) * 128 + (k0 & 63) * 2);
        uint32_t sw = SMEM_SWIZZLE_128B(byte_off);
        *(uint2*)(smem + XW_AHI + sw) = make_uint2(pack2bf16(hx, hy), pack2bf16(hz, hw));
        *(uint2*)(smem + XW_ALO + sw) = make_uint2(pack2bf16(lx, ly), pack2bf16(lz, lw));
    }
}

// Issue 2 N-chunk x 3-pass x 6-Kstep MMA chain into D at dbase; commit to mbar.
__device__ __forceinline__ void issue_mma_96(uint32_t smem_base, uint32_t dbase,
                                             uint32_t mbar)
{
    const uint32_t a_reg[3] = { XW_AHI, XW_ALO, XW_AHI };
    const uint32_t b_reg[3] = { XW_BHI, XW_BHI, XW_BLO };
#pragma unroll
    for (int c = 0; c < 2; c++) {
        const uint32_t n0 = (uint32_t)c * 64;
        const uint32_t nn = (c == 0) ? 64u : 32u;
        const uint32_t idesc = (1u << 4) | (1u << 7) | (1u << 10)
                             | ((nn / 8u) << 17) | (8u << 24);
        bool first = true;
#pragma unroll
        for (int p = 0; p < 3; p++) {
#pragma unroll
            for (int j = 0; j < 6; j++) {
                uint32_t a_addr = smem_base + a_reg[p]
                                + (uint32_t)((j >> 2) * 16384 + (j & 3) * 32);
                uint32_t b_addr = smem_base + b_reg[p]
                                + (uint32_t)((j >> 2) * 12288 + (j & 3) * 32)
                                + n0 * 128u;
                mma_f16_ss(dbase + n0,
                           MAKE_SMEM_DESC(a_addr), MAKE_SMEM_DESC(b_addr),
                           idesc, !first);
                first = false;
            }
        }
    }
    TCGEN05_COMMIT(mbar);
}
#endif // TC_OK

// ============================================================
// x@W via tcgen05: pipelined multi-tile blocks (single A buffer,
// D ping-pong; epilogue(it-1) overlaps MMA(it)).
// ============================================================
__global__ void __launch_bounds__(256) xw_mma_kernel(
    const uint32_t* __restrict__ Bimg, const float* __restrict__ X,
    const float* __restrict__ Wfb, float* __restrict__ M, int nrows)
{
    extern __shared__ char smem[];
    const int t = threadIdx.x;

    const int ntiles = (nrows + 127) >> 7;
    const int tile0  = blockIdx.x * XW_TILES;
    int nact = ntiles - tile0;
    if (nact <= 0) return;
    if (nact > XW_TILES) nact = XW_TILES;

#if TC_OK
    const uint32_t smem_base = smem_to_u32(smem);
    const int wid  = t >> 5;
    const int lane = t & 31;

    if (wid == 0) {
        TCGEN05_ALLOC(smem_base, 256);
        TCGEN05_RELINQUISH();
    }
    if (t == 0) MBARRIER_INIT(smem_base + 8, 1);

    // B: copy layer image once
    {
        const uint4* src = (const uint4*)Bimg;
        uint4* dst = (uint4*)(smem + XW_BHI);
#pragma unroll
        for (int i = 0; i < 12; i++) dst[t + i * 256] = src[t + i * 256];
    }

    __syncthreads();
    uint32_t tmem_base;
    asm volatile("ld.shared.b32 %0, [%1];" : "=r"(tmem_base) : "r"(smem_base));

    for (int it = 0; it < nact; it++) {
        const int row0 = (tile0 + it) * 128;

        if (it > 0) {
            MBARRIER_WAIT_PARITY(smem_base + 8, (it - 1) & 1);
            TCGEN05_FENCE_AFTER();
        }

        convert_A_tile(X, row0, nrows, smem, t);
        FENCE_PROXY_ASYNC();
        __syncthreads();

        if (wid == 0) {
            TCGEN05_FENCE_AFTER();
            if (elect_one_pred())
                issue_mma_96(smem_base, tmem_base + (uint32_t)(it & 1) * 128,
                             smem_base + 8);
        }

        if (it > 0) {
            const int prow0 = (tile0 + it - 1) * 128;
            const uint32_t dbase = tmem_base + (uint32_t)((it - 1) & 1) * 128;
            const int sub = wid & 3;
            const int row = prow0 + sub * 32 + lane;
            const int nch = (wid < 4) ? 2 : 1;
            const int cst = (wid < 4) ? 0 : 64;
            for (int ch = 0; ch < nch; ch++) {
                int c0 = cst + ch * 32;
                uint32_t d[32];
                TCGEN05_LD_32X32B_X32(d, dbase + c0);
                TCGEN05_WAIT_LD();
                if (row < nrows) {
                    float4* op = (float4*)(M + (size_t)row * C + c0);
#pragma unroll
                    for (int i = 0; i < 8; i++) {
                        float4 v;
                        v.x = __uint_as_float(d[4 * i + 0]);
                        v.y = __uint_as_float(d[4 * i + 1]);
                        v.z = __uint_as_float(d[4 * i + 2]);
                        v.w = __uint_as_float(d[4 * i + 3]);
                        op[i] = v;
                    }
                }
            }
        }
    }

    MBARRIER_WAIT_PARITY(smem_base + 8, (nact - 1) & 1);
    TCGEN05_FENCE_AFTER();
    {
        const int prow0 = (tile0 + nact - 1) * 128;
        const uint32_t dbase = tmem_base + (uint32_t)((nact - 1) & 1) * 128;
        const int sub = wid & 3;
        const int row = prow0 + sub * 32 + lane;
        const int nch = (wid < 4) ? 2 : 1;
        const int cst = (wid < 4) ? 0 : 64;
        for (int ch = 0; ch < nch; ch++) {
            int c0 = cst + ch * 32;
            uint32_t d[32];
            TCGEN05_LD_32X32B_X32(d, dbase + c0);
            TCGEN05_WAIT_LD();
            if (row < nrows) {
                float4* op = (float4*)(M + (size_t)row * C + c0);
#pragma unroll
                for (int i = 0; i < 8; i++) {
                    float4 v;
                    v.x = __uint_as_float(d[4 * i + 0]);
                    v.y = __uint_as_float(d[4 * i + 1]);
                    v.z = __uint_as_float(d[4 * i + 2]);
                    v.w = __uint_as_float(d[4 * i + 3]);
                    op[i] = v;
                }
            }
        }
    }

    __syncthreads();
    if (wid == 0) {
        TCGEN05_DEALLOC(tmem_base, 256);
    }
#else
    for (int it = 0; it < nact; it++) {
        int row0 = (tile0 + it) * 128;
        for (int idx = t; idx < 128 * 96; idx += 256) {
            int r = idx / 96, c = idx - r * 96;
            int gr = row0 + r;
            if (gr < nrows) {
                float s = 0.f;
                for (int k = 0; k < 96; k++) s = fmaf(X[gr * 96 + k], Wfb[k * 96 + c], s);
                M[(size_t)gr * C + c] = s;
            }
        }
    }
#endif
}

// ============================================================
// Gates GEMM: pipelined 8-tile blocks; grid (ceil(nt/8), 6).
// y&1 -> gi/gh, y>>1 -> N-third h.
// ============================================================
__global__ void __launch_bounds__(256) gates_mma_kernel(
    const float* __restrict__ A0, const float* __restrict__ A1,
    const float* __restrict__ bias0, const float* __restrict__ bias1,
    float* __restrict__ O0, float* __restrict__ O1, int nrows)
{
    extern __shared__ char smem[];
    const int t = threadIdx.x;
    const int y = blockIdx.y & 1;
    const int h = blockIdx.y >> 1;             // gate cols [96h, 96h+96)

    const float* A    = y ? A1 : A0;
    const float* bias = y ? bias1 : bias0;
    float*       O    = y ? O1 : O0;

    const int ntiles = (nrows + 127) >> 7;
    const int tile0  = blockIdx.x * GATES_TILES;
    int nact = ntiles - tile0;
    if (nact <= 0) return;
    if (nact > GATES_TILES) nact = GATES_TILES;

#if TC_OK
    const uint32_t smem_base = smem_to_u32(smem);
    const int wid  = t >> 5;
    const int lane = t & 31;

    if (wid == 0) {
        TCGEN05_ALLOC(smem_base, 256);       // 2 x 128-col D ping-pong
        TCGEN05_RELINQUISH();
    }
    if (t == 0) MBARRIER_INIT(smem_base + 8, 1);

    // B: copy 96-row slice of the W image (once per block)
    {
        const uint4* src = (const uint4*)(g_wimg[y]);
        uint4* dsth = (uint4*)(smem + XW_BHI);
        uint4* dstl = (uint4*)(smem + XW_BLO);
        const int b0 = (12 * h) * 64;
        const int b1 = (36 + 12 * h) * 64;
#pragma unroll
        for (int i = 0; i < 3; i++) {
            int o = t + i * 256;
            dsth[o]        = src[b0 + o];
            dsth[768 + o]  = src[b1 + o];
            dstl[o]        = src[4608 + b0 + o];
            dstl[768 + o]  = src[4608 + b1 + o];
        }
    }

    __syncthreads();
    uint32_t tmem_base;
    asm volatile("ld.shared.b32 %0, [%1];" : "=r"(tmem_base) : "r"(smem_base));

    const float4* b4 = (const float4*)bias;

    for (int it = 0; it < nact; it++) {
        const int row0 = (tile0 + it) * 128;

        if (it > 0) {
            MBARRIER_WAIT_PARITY(smem_base + 8, (it - 1) & 1);
            TCGEN05_FENCE_AFTER();
        }

        convert_A_tile(A, row0, nrows, smem, t);
        FENCE_PROXY_ASYNC();
        __syncthreads();

        if (wid == 0) {
            TCGEN05_FENCE_AFTER();
            if (elect_one_pred())
                issue_mma_96(smem_base, tmem_base + (uint32_t)(it & 1) * 128,
                             smem_base + 8);
        }

        if (it > 0) {
            const int prow0 = (tile0 + it - 1) * 128;
            const uint32_t dbase = tmem_base + (uint32_t)((it - 1) & 1) * 128;
            const int sub = wid & 3;
            const int row = prow0 + sub * 32 + lane;
            const int nch = (wid < 4) ? 2 : 1;
            const int cst = (wid < 4) ? 0 : 64;
            for (int ch = 0; ch < nch; ch++) {
                int c0 = cst + ch * 32;
                uint32_t d[32];
                TCGEN05_LD_32X32B_X32(d, dbase + c0);
                TCGEN05_WAIT_LD();
                if (row < nrows) {
                    int gc = h * 96 + c0;
                    float4* op = (float4*)(O + (size_t)row * GATE + gc);
#pragma unroll
                    for (int i = 0; i < 8; i++) {
                        float4 bb = __ldg(&b4[gc / 4 + i]);
                        float4 v;
                        v.x = __uint_as_float(d[4 * i + 0]) + bb.x;
                        v.y = __uint_as_float(d[4 * i + 1]) + bb.y;
                        v.z = __uint_as_float(d[4 * i + 2]) + bb.z;
                        v.w = __uint_as_float(d[4 * i + 3]) + bb.w;
                        op[i] = v;
                    }
                }
            }
        }
    }

    // final tile epilogue
    MBARRIER_WAIT_PARITY(smem_base + 8, (nact - 1) & 1);
    TCGEN05_FENCE_AFTER();
    {
        const int prow0 = (tile0 + nact - 1) * 128;
        const uint32_t dbase = tmem_base + (uint32_t)((nact - 1) & 1) * 128;
        const int sub = wid & 3;
        const int row = prow0 + sub * 32 + lane;
        const int nch = (wid < 4) ? 2 : 1;
        const int cst = (wid < 4) ? 0 : 64;
        for (int ch = 0; ch < nch; ch++) {
            int c0 = cst + ch * 32;
            uint32_t d[32];
            TCGEN05_LD_32X32B_X32(d, dbase + c0);
            TCGEN05_WAIT_LD();
            if (row < nrows) {
                int gc = h * 96 + c0;
                float4* op = (float4*)(O + (size_t)row * GATE + gc);
#pragma unroll
                for (int i = 0; i < 8; i++) {
                    float4 bb = __ldg(&b4[gc / 4 + i]);
                    float4 v;
                    v.x = __uint_as_float(d[4 * i + 0]) + bb.x;
                    v.y = __uint_as_float(d[4 * i + 1]) + bb.y;
                    v.z = __uint_as_float(d[4 * i + 2]) + bb.z;
                    v.w = __uint_as_float(d[4 * i + 3]) + bb.w;
                    op[i] = v;
                }
            }
        }
    }

    __syncthreads();
    if (wid == 0) {
        TCGEN05_DEALLOC(tmem_base, 256);
    }
#else
    // SIMT fallback (never runs on HW)
    for (int it = 0; it < nact; it++) {
        int row0 = (tile0 + it) * 128;
        for (int idx = t; idx < 128 * 96; idx += 256) {
            int r = idx / 96, cl = idx - r * 96;
            int c = h * 96 + cl;
            int gr = row0 + r;
            if (gr < nrows) {
                float s = bias[c];
                for (int k = 0; k < 96; k++) {
                    uint32_t byte_off = (uint32_t)(((c >> 3) + (k >> 6) * 36) * 1024
                                                   + (c & 7) * 128 + (k & 63) * 2);
                    uint32_t slot = SMEM_SWIZZLE_128B(byte_off & ~3u) >> 2;
                    uint32_t hv = g_wimg[y][slot];
                    uint32_t lv = g_wimg[y][slot + 18432];
                    int sh = (k & 1) ? 16 : 0;
                    float wh = __bfloat162float(__ushort_as_bfloat16((unsigned short)(hv >> sh)));
                    float wl = __bfloat162float(__ushort_as_bfloat16((unsigned short)(lv >> sh)));
                    s = fmaf(A[gr * 96 + k], wh + wl, s);
                }
                O[(size_t)gr * GATE + c] = s;
            }
        }
    }
#endif
}

// ============================================================
// GRU elementwise
// ============================================================
__device__ __forceinline__ float gru_one(float ir, float iz, float inn,
                                         float hr, float hz, float hn, float h)
{
    float r = 1.f / (1.f + expf(-(ir + hr)));
    float z = 1.f / (1.f + expf(-(iz + hz)));
    float n = tanhf(inn + r * hn);
    return (1.f - z) * n + z * h;
}

__global__ void gru_kernel(const float* __restrict__ GI,
                           const float* __restrict__ GH,
                           const float* __restrict__ H,
                           float* __restrict__ OUT,
                           int nrows)
{
    int tid = blockIdx.x * blockDim.x + threadIdx.x;
    int total = nrows * 24;
    if (tid >= total) return;
    int n = tid / 24;
    int q = tid - n * 24;

    const float4* gi4 = (const float4*)GI;
    const float4* gh4 = (const float4*)GH;
    float4 ir  = gi4[n * 72 + q];
    float4 iz  = gi4[n * 72 + 24 + q];
    float4 inn = gi4[n * 72 + 48 + q];
    float4 hr  = gh4[n * 72 + q];
    float4 hz  = gh4[n * 72 + 24 + q];
    float4 hn  = gh4[n * 72 + 48 + q];
    float4 h   = ((const float4*)H)[n * 24 + q];

    float4 o;
    o.x = gru_one(ir.x, iz.x, inn.x, hr.x, hz.x, hn.x, h.x);
    o.y = gru_one(ir.y, iz.y, inn.y, hr.y, hz.y, hn.y, h.y);
    o.z = gru_one(ir.z, iz.z, inn.z, hr.z, hz.z, hn.z, h.z);
    o.w = gru_one(ir.w, iz.w, inn.w, hr.w, hz.w, hn.w, h.w);

    ((float4*)OUT)[n * 24 + q] = o;
}

// ============================================================
extern "C" void kernel_launch(void* const* d_in, const int* in_sizes, int n_in,
                              void* d_out, int out_size)
{
    const float* x      = (const float*)d_in[0];
    const int*   ei     = (const int*)  d_in[1];
    const float* weight = (const float*)d_in[2];
    const float* w_ih   = (const float*)d_in[3];
    const float* w_hh   = (const float*)d_in[4];
    const float* b_ih   = (const float*)d_in[5];
    const float* b_hh   = (const float*)d_in[6];
    float* out = (float*)d_out;

    const int nrows  = in_sizes[0] / C;
    const int nedges = in_sizes[1] / 2;

    float *pm, *pagg, *pgi, *pgh, *px1, *px2;
    uint32_t* pwx;
    cudaGetSymbolAddress((void**)&pm,   g_m);
    cudaGetSymbolAddress((void**)&pagg, g_agg);
    cudaGetSymbolAddress((void**)&pgi,  g_gi);
    cudaGetSymbolAddress((void**)&pgh,  g_gh);
    cudaGetSymbolAddress((void**)&px1,  g_x1);
    cudaGetSymbolAddress((void**)&px2,  g_x2);
    cudaGetSymbolAddress((void**)&pwx,  g_wximg);

    cudaFuncSetAttribute(xw_mma_kernel,    cudaFuncAttributeMaxDynamicSharedMemorySize, XW_TOTAL);
    cudaFuncSetAttribute(gates_mma_kernel, cudaFuncAttributeMaxDynamicSharedMemorySize, XW_TOTAL);

    const int rblocks128 = (nrows + 127) / 128;
    const int gblocks    = (rblocks128 + GATES_TILES - 1) / GATES_TILES;
    const int xblocks    = (rblocks128 + XW_TILES - 1) / XW_TILES;
    dim3 g_gates(gblocks, 6);
    const int gru_blocks = (nrows * 24 + 255) / 256;
    const int agg_blocks = (nrows * 32 + 255) / 256;
    const int nb256      = (nrows + 255) / 256;

    // Precompute: W images + CSR (layer-invariant)
    conv_w_kernel<<<(2 * 288 * 64 + 255) / 256, 256>>>(w_ih, w_hh);
    conv_wx_kernel<<<(3 * 96 * 64 + 255) / 256, 256>>>(weight);
    csr_zero_kernel<<<nb256, 256>>>(nrows);
    csr_count_kernel<<<(nedges + 255) / 256, 256>>>(ei, nedges);
    scan1_kernel<<<nb256, 256>>>(nrows);
    scan2_kernel<<<1, 256>>>(nb256, nrows);
    scan3_kernel<<<nb256, 256>>>(nrows);
    csr_fill_kernel<<<(nedges + 255) / 256, 256>>>(ei, nedges);

    const float* xin = x;
    float* xbufs[3] = {px1, px2, out};

    for (int l = 0; l < 3; l++) {
        float* xout = xbufs[l];
        xw_mma_kernel<<<xblocks, 256, XW_TOTAL>>>(pwx + l * 12288, xin,
                                                  weight + l * C * C, pm, nrows);
        agg_kernel<<<agg_blocks, 256>>>(pm, pagg, nrows);
        gates_mma_kernel<<<g_gates, 256, XW_TOTAL>>>(pagg, xin, b_ih, b_hh,
                                                     pgi, pgh, nrows);
        gru_kernel<<<gru_blocks, 256>>>(pgi, pgh, xin, xout, nrows);
        xin = xout;
    }
}

// round 15
// speedup vs baseline: 1.0914x; 1.0082x over previous
#include <cuda_runtime.h>
#include <cuda_bf16.h>
#include <math.h>
#include <cstdint>

#define N_NODES 50000
#define N_EDGES 800000
#define C 96
#define GATE 288   // 3*C

#if defined(__CUDA_ARCH_FEAT_SM103_ALL) || defined(__CUDA_ARCH_FEAT_SM100_ALL)
#define TC_OK 1
#else
#define TC_OK 0
#endif

// ---- scratch (device globals; no allocations allowed) ----
__device__ float g_m  [N_NODES * C];
__device__ float g_agg[N_NODES * C];
__device__ float g_gi [N_NODES * GATE];
__device__ float g_gh [N_NODES * GATE];
__device__ float g_x1 [N_NODES * C];
__device__ float g_x2 [N_NODES * C];
__device__ uint32_t g_wimg [2][36864];   // gates W images (hi|lo)
__device__ uint32_t g_wximg[3][12288];   // per-layer x@W images (hi|lo)
// CSR
__device__ int g_deg [N_NODES];
__device__ int g_fill[N_NODES];
__device__ int g_off [N_NODES + 1];
__device__ int g_csr [N_EDGES];
__device__ int g_bsum[256];

// ============================================================
// PTX helpers
// ============================================================
__device__ __forceinline__ uint32_t smem_to_u32(const void* p) {
    uint32_t a;
    asm("{ .reg .u64 t; cvta.to.shared.u64 t, %1; cvt.u32.u64 %0, t; }" : "=r"(a) : "l"(p));
    return a;
}

#if TC_OK
__device__ __forceinline__ uint32_t elect_one_pred() {
    uint32_t pred;
    asm volatile("{\n\t.reg .pred p;\n\telect.sync _|p, 0xFFFFFFFF;\n\tselp.b32 %0, 1, 0, p;\n\t}" : "=r"(pred));
    return pred;
}
#define TCGEN05_ALLOC(smem_addr, nCols) \
    asm volatile("tcgen05.alloc.cta_group::1.sync.aligned.shared::cta.b32 [%0], %1;" \
        :: "r"((uint32_t)(smem_addr)), "r"((uint32_t)(nCols)) : "memory")
#define TCGEN05_DEALLOC(tmem, nCols) \
    asm volatile("tcgen05.dealloc.cta_group::1.sync.aligned.b32 %0, %1;" :: "r"(tmem), "r"((uint32_t)(nCols)))
#define TCGEN05_RELINQUISH() \
    asm volatile("tcgen05.relinquish_alloc_permit.cta_group::1.sync.aligned;")
#define TCGEN05_COMMIT(mbar) \
    asm volatile("tcgen05.commit.cta_group::1.mbarrier::arrive::one.shared::cluster.b64 [%0];" \
        :: "r"((uint32_t)(mbar)) : "memory")
#define TCGEN05_WAIT_LD() asm volatile("tcgen05.wait::ld.sync.aligned;" ::: "memory")
#define TCGEN05_FENCE_AFTER() asm volatile("tcgen05.fence::after_thread_sync;" ::: "memory")
#define FENCE_PROXY_ASYNC() asm volatile("fence.proxy.async.shared::cta;" ::: "memory")
#define MBARRIER_INIT(mbar, cnt) \
    asm volatile("mbarrier.init.shared.b64 [%0], %1;" :: "r"((uint32_t)(mbar)), "r"((uint32_t)(cnt)) : "memory")
#define MBARRIER_WAIT_PARITY(mbar, parity) do { \
    uint32_t _m = (uint32_t)(mbar); uint32_t _p = (uint32_t)(parity); uint32_t _d; \
    asm volatile("{\n\t.reg .pred p;\n\tmbarrier.try_wait.parity.acquire.cta.shared::cta.b64 p, [%1], %2;\n\tselp.b32 %0, 1, 0, p;\n\t}" \
        : "=r"(_d) : "r"(_m), "r"(_p) : "memory"); \
    if (!_d) { \
        asm volatile("{\n\t.reg .pred P1;\n\tWL_%=:\n\tmbarrier.try_wait.parity.acquire.cta.shared::cta.b64 P1, [%0], %1, 0x989680;\n\t@P1 bra.uni WD_%=;\n\tbra.uni WL_%=;\n\tWD_%=:\n\t}" \
            :: "r"(_m), "r"(_p) : "memory"); \
    } } while (0)
#define TCGEN05_LD_32X32B_X32(r, tmem_addr) \
    asm volatile( \
        "tcgen05.ld.sync.aligned.32x32b.x32.b32 " \
        "{%0, %1, %2, %3, %4, %5, %6, %7, " \
        " %8, %9, %10, %11, %12, %13, %14, %15, " \
        " %16, %17, %18, %19, %20, %21, %22, %23, " \
        " %24, %25, %26, %27, %28, %29, %30, %31}, [%32];" \
        : "=r"((r)[0]),  "=r"((r)[1]),  "=r"((r)[2]),  "=r"((r)[3]), \
          "=r"((r)[4]),  "=r"((r)[5]),  "=r"((r)[6]),  "=r"((r)[7]), \
          "=r"((r)[8]),  "=r"((r)[9]),  "=r"((r)[10]), "=r"((r)[11]), \
          "=r"((r)[12]), "=r"((r)[13]), "=r"((r)[14]), "=r"((r)[15]), \
          "=r"((r)[16]), "=r"((r)[17]), "=r"((r)[18]), "=r"((r)[19]), \
          "=r"((r)[20]), "=r"((r)[21]), "=r"((r)[22]), "=r"((r)[23]), \
          "=r"((r)[24]), "=r"((r)[25]), "=r"((r)[26]), "=r"((r)[27]), \
          "=r"((r)[28]), "=r"((r)[29]), "=r"((r)[30]), "=r"((r)[31]) \
        : "r"(tmem_addr))

__device__ __forceinline__ void mma_f16_ss(uint32_t d, uint64_t ad, uint64_t bd,
                                           uint32_t idesc, bool accum) {
    uint32_t en = accum ? 1u : 0u;
    uint32_t z = 0;
    asm volatile(
        "{\n\t.reg .pred p;\n\tsetp.ne.u32 p, %5, 0;\n\t"
        "tcgen05.mma.cta_group::1.kind::f16 [%0], %1, %2, %3, {%4, %4, %4, %4}, p;\n\t}"
        :: "r"(d), "l"(ad), "l"(bd), "r"(idesc), "r"(z), "r"(en) : "memory");
}
#endif // TC_OK

static constexpr uint64_t SMEM_DESC_BASE_SW128 =
    (uint64_t(2)  << 61) | (uint64_t(1) << 46) | (uint64_t(64) << 32) | (uint64_t(1) << 16);
#define MAKE_SMEM_DESC(base_addr) (SMEM_DESC_BASE_SW128 | ((uint64_t)((base_addr) >> 4) & 0x3FFF))
#define SMEM_SWIZZLE_128B(b) ((b) ^ (((b) >> 3) & 0x70))

__device__ __forceinline__ uint32_t pack2bf16(__nv_bfloat16 a, __nv_bfloat16 b) {
    __nv_bfloat162 t = __halves2bfloat162(a, b);
    return *reinterpret_cast<uint32_t*>(&t);
}

// ============================================================
// CSR build
// ============================================================
__global__ void csr_zero_kernel(int nrows)
{
    int t = blockIdx.x * blockDim.x + threadIdx.x;
    if (t < nrows) { g_deg[t] = 0; g_fill[t] = 0; }
}

__global__ void csr_count_kernel(const int* __restrict__ ei, int nedges)
{
    int t = blockIdx.x * blockDim.x + threadIdx.x;
    if (t < nedges) atomicAdd(&g_deg[ei[nedges + t]], 1);
}

__global__ void scan1_kernel(int nrows)
{
    __shared__ int s[256];
    const int t = threadIdx.x;
    int idx = blockIdx.x * 256 + t;
    int d = (idx < nrows) ? g_deg[idx] : 0;
    s[t] = d;
    __syncthreads();
#pragma unroll
    for (int o = 1; o < 256; o <<= 1) {
        int v = (t >= o) ? s[t - o] : 0;
        __syncthreads();
        s[t] += v;
        __syncthreads();
    }
    if (idx < nrows) g_off[idx] = s[t] - d;
    if (t == 255) g_bsum[blockIdx.x] = s[255];
}

__global__ void scan2_kernel(int nblocks, int nrows)
{
    __shared__ int s[256];
    const int t = threadIdx.x;
    int b = (t < nblocks) ? g_bsum[t] : 0;
    s[t] = b;
    __syncthreads();
#pragma unroll
    for (int o = 1; o < 256; o <<= 1) {
        int v = (t >= o) ? s[t - o] : 0;
        __syncthreads();
        s[t] += v;
        __syncthreads();
    }
    if (t < nblocks) g_bsum[t] = s[t] - b;
    if (t == 255) g_off[nrows] = s[255];
}

__global__ void scan3_kernel(int nrows)
{
    int idx = blockIdx.x * 256 + threadIdx.x;
    if (idx < nrows) g_off[idx] += g_bsum[blockIdx.x];
}

__global__ void csr_fill_kernel(const int* __restrict__ ei, int nedges)
{
    int t = blockIdx.x * blockDim.x + threadIdx.x;
    if (t >= nedges) return;
    int dst = ei[nedges + t];
    int pos = g_off[dst] + atomicAdd(&g_fill[dst], 1);
    g_csr[pos] = ei[t];
}

// ============================================================
// Aggregation: one warp per dst row; lanes 0-23 accumulate float4.
// ============================================================
__global__ void agg_kernel(const float* __restrict__ m,
                           float* __restrict__ agg, int nrows)
{
    int w    = (blockIdx.x * blockDim.x + threadIdx.x) >> 5;
    int lane = threadIdx.x & 31;
    if (w >= nrows || lane >= 24) return;

    const int beg = g_off[w];
    const int end = g_off[w + 1];
    const float4* m4 = (const float4*)m;

    float4 acc = make_float4(0.f, 0.f, 0.f, 0.f);
    int e = beg;
    for (; e + 1 < end; e += 2) {
        int s0 = g_csr[e];
        int s1 = g_csr[e + 1];
        float4 v0 = m4[s0 * 24 + lane];
        float4 v1 = m4[s1 * 24 + lane];
        acc.x += v0.x + v1.x;
        acc.y += v0.y + v1.y;
        acc.z += v0.z + v1.z;
        acc.w += v0.w + v1.w;
    }
    if (e < end) {
        float4 v = m4[g_csr[e] * 24 + lane];
        acc.x += v.x; acc.y += v.y; acc.z += v.z; acc.w += v.w;
    }
    ((float4*)agg)[w * 24 + lane] = acc;
}

// ============================================================
// Precompute swizzled bf16 hi/lo weight images
// ============================================================
__global__ void conv_w_kernel(const float* __restrict__ w_ih,
                              const float* __restrict__ w_hh)
{
    int tid = blockIdx.x * blockDim.x + threadIdx.x;
    if (tid >= 2 * 288 * 64) return;
    int tsr = tid / (288 * 64);
    int rem = tid - tsr * (288 * 64);
    int n  = rem >> 6;
    int k  = (rem & 63) * 2;
    const float* W = tsr ? w_hh : w_ih;

    float v0 = 0.f, v1 = 0.f;
    if (k < 96) { v0 = W[n * 96 + k]; v1 = W[n * 96 + k + 1]; }
    __nv_bfloat16 h0 = __float2bfloat16_rn(v0);
    __nv_bfloat16 h1 = __float2bfloat16_rn(v1);
    __nv_bfloat16 l0 = __float2bfloat16_rn(v0 - __bfloat162float(h0));
    __nv_bfloat16 l1 = __float2bfloat16_rn(v1 - __bfloat162float(h1));

    uint32_t byte_off = (uint32_t)(((n >> 3) + (k >> 6) * 36) * 1024
                                   + (n & 7) * 128 + (k & 63) * 2);
    uint32_t slot = SMEM_SWIZZLE_128B(byte_off) >> 2;
    g_wimg[tsr][slot]         = pack2bf16(h0, h1);
    g_wimg[tsr][slot + 18432] = pack2bf16(l0, l1);
}

__global__ void conv_wx_kernel(const float* __restrict__ weight)
{
    int tid = blockIdx.x * blockDim.x + threadIdx.x;
    if (tid >= 3 * 96 * 64) return;
    int l   = tid / (96 * 64);
    int rem = tid - l * (96 * 64);
    int n  = rem >> 6;
    int k  = (rem & 63) * 2;
    const float* W = weight + l * C * C;

    float v0 = 0.f, v1 = 0.f;
    if (k < 96) { v0 = W[k * 96 + n]; v1 = W[(k + 1) * 96 + n]; }
    __nv_bfloat16 h0 = __float2bfloat16_rn(v0);
    __nv_bfloat16 h1 = __float2bfloat16_rn(v1);
    __nv_bfloat16 l0 = __float2bfloat16_rn(v0 - __bfloat162float(h0));
    __nv_bfloat16 l1 = __float2bfloat16_rn(v1 - __bfloat162float(h1));

    uint32_t byte_off = (uint32_t)(((n >> 3) + (k >> 6) * 12) * 1024
                                   + (n & 7) * 128 + (k & 63) * 2);
    uint32_t slot = SMEM_SWIZZLE_128B(byte_off) >> 2;
    g_wximg[l][slot]        = pack2bf16(h0, h1);
    g_wximg[l][slot + 6144] = pack2bf16(l0, l1);
}

// ============================================================
// Shared 128x96-tile MMA block shape (smem 115712; regs capped 128
// via __launch_bounds__(256,2) -> true 2 CTAs/SM)
// ============================================================
#define XW_AHI    1024
#define XW_ALO    (XW_AHI + 32768)     // 33792
#define XW_BHI    (XW_ALO + 32768)     // 66560
#define XW_BLO    (XW_BHI + 24576)     // 91136
#define XW_TOTAL  (XW_BLO + 24576)     // 115712

#define GATES_TILES 8
#define XW_TILES    2

#if TC_OK
// Convert fp32 A tile -> hi/lo bf16 blocked atoms in smem.
__device__ __forceinline__ void convert_A_tile(
    const float* __restrict__ A, int row0, int nrows, char* smem, int t)
{
    const float4* A4 = (const float4*)A;
#pragma unroll
    for (int i = 0; i < 12; i++) {
        int idx = t + i * 256;
        int r = idx / 24, q = idx - r * 24;
        int k0 = q * 4;
        int grow = row0 + r;
        float4 v = make_float4(0.f, 0.f, 0.f, 0.f);
        if (grow < nrows) v = A4[grow * 24 + q];

        __nv_bfloat16 hx = __float2bfloat16_rn(v.x);
        __nv_bfloat16 hy = __float2bfloat16_rn(v.y);
        __nv_bfloat16 hz = __float2bfloat16_rn(v.z);
        __nv_bfloat16 hw = __float2bfloat16_rn(v.w);
        __nv_bfloat16 lx = __float2bfloat16_rn(v.x - __bfloat162float(hx));
        __nv_bfloat16 ly = __float2bfloat16_rn(v.y - __bfloat162float(hy));
        __nv_bfloat16 lz = __float2bfloat16_rn(v.z - __bfloat162float(hz));
        __nv_bfloat16 lw = __float2bfloat16_rn(v.w - __bfloat162float(hw));

        uint32_t byte_off = (uint32_t)(((r >> 3) + (k0 >> 6) * 16) * 1024
                                       + (r & 7) * 128 + (k0 & 63) * 2);
        uint32_t sw = SMEM_SWIZZLE_128B(byte_off);
        *(uint2*)(smem + XW_AHI + sw) = make_uint2(pack2bf16(hx, hy), pack2bf16(hz, hw));
        *(uint2*)(smem + XW_ALO + sw) = make_uint2(pack2bf16(lx, ly), pack2bf16(lz, lw));
    }
}

// Issue 2 N-chunk x 3-pass x 6-Kstep MMA chain into D at dbase; commit to mbar.
__device__ __forceinline__ void issue_mma_96(uint32_t smem_base, uint32_t dbase,
                                             uint32_t mbar)
{
    const uint32_t a_reg[3] = { XW_AHI, XW_ALO, XW_AHI };
    const uint32_t b_reg[3] = { XW_BHI, XW_BHI, XW_BLO };
#pragma unroll
    for (int c = 0; c < 2; c++) {
        const uint32_t n0 = (uint32_t)c * 64;
        const uint32_t nn = (c == 0) ? 64u : 32u;
        const uint32_t idesc = (1u << 4) | (1u << 7) | (1u << 10)
                             | ((nn / 8u) << 17) | (8u << 24);
        bool first = true;
#pragma unroll
        for (int p = 0; p < 3; p++) {
#pragma unroll
            for (int j = 0; j < 6; j++) {
                uint32_t a_addr = smem_base + a_reg[p]
                                + (uint32_t)((j >> 2) * 16384 + (j & 3) * 32);
                uint32_t b_addr = smem_base + b_reg[p]
                                + (uint32_t)((j >> 2) * 12288 + (j & 3) * 32)
                                + n0 * 128u;
                mma_f16_ss(dbase + n0,
                           MAKE_SMEM_DESC(a_addr), MAKE_SMEM_DESC(b_addr),
                           idesc, !first);
                first = false;
            }
        }
    }
    TCGEN05_COMMIT(mbar);
}
#endif // TC_OK

// ============================================================
// x@W via tcgen05: pipelined multi-tile blocks (single A buffer,
// D ping-pong; epilogue(it-1) overlaps MMA(it)).
// ============================================================
__global__ void __launch_bounds__(256, 2) xw_mma_kernel(
    const uint32_t* __restrict__ Bimg, const float* __restrict__ X,
    const float* __restrict__ Wfb, float* __restrict__ M, int nrows)
{
    extern __shared__ char smem[];
    const int t = threadIdx.x;

    const int ntiles = (nrows + 127) >> 7;
    const int tile0  = blockIdx.x * XW_TILES;
    int nact = ntiles - tile0;
    if (nact <= 0) return;
    if (nact > XW_TILES) nact = XW_TILES;

#if TC_OK
    const uint32_t smem_base = smem_to_u32(smem);
    const int wid  = t >> 5;
    const int lane = t & 31;

    if (wid == 0) {
        TCGEN05_ALLOC(smem_base, 256);
        TCGEN05_RELINQUISH();
    }
    if (t == 0) MBARRIER_INIT(smem_base + 8, 1);

    // B: copy layer image once
    {
        const uint4* src = (const uint4*)Bimg;
        uint4* dst = (uint4*)(smem + XW_BHI);
#pragma unroll
        for (int i = 0; i < 12; i++) dst[t + i * 256] = src[t + i * 256];
    }

    __syncthreads();
    uint32_t tmem_base;
    asm volatile("ld.shared.b32 %0, [%1];" : "=r"(tmem_base) : "r"(smem_base));

    for (int it = 0; it < nact; it++) {
        const int row0 = (tile0 + it) * 128;

        if (it > 0) {
            MBARRIER_WAIT_PARITY(smem_base + 8, (it - 1) & 1);
            TCGEN05_FENCE_AFTER();
        }

        convert_A_tile(X, row0, nrows, smem, t);
        FENCE_PROXY_ASYNC();
        __syncthreads();

        if (wid == 0) {
            TCGEN05_FENCE_AFTER();
            if (elect_one_pred())
                issue_mma_96(smem_base, tmem_base + (uint32_t)(it & 1) * 128,
                             smem_base + 8);
        }

        if (it > 0) {
            const int prow0 = (tile0 + it - 1) * 128;
            const uint32_t dbase = tmem_base + (uint32_t)((it - 1) & 1) * 128;
            const int sub = wid & 3;
            const int row = prow0 + sub * 32 + lane;
            const int nch = (wid < 4) ? 2 : 1;
            const int cst = (wid < 4) ? 0 : 64;
            for (int ch = 0; ch < nch; ch++) {
                int c0 = cst + ch * 32;
                uint32_t d[32];
                TCGEN05_LD_32X32B_X32(d, dbase + c0);
                TCGEN05_WAIT_LD();
                if (row < nrows) {
                    float4* op = (float4*)(M + (size_t)row * C + c0);
#pragma unroll
                    for (int i = 0; i < 8; i++) {
                        float4 v;
                        v.x = __uint_as_float(d[4 * i + 0]);
                        v.y = __uint_as_float(d[4 * i + 1]);
                        v.z = __uint_as_float(d[4 * i + 2]);
                        v.w = __uint_as_float(d[4 * i + 3]);
                        op[i] = v;
                    }
                }
            }
        }
    }

    MBARRIER_WAIT_PARITY(smem_base + 8, (nact - 1) & 1);
    TCGEN05_FENCE_AFTER();
    {
        const int prow0 = (tile0 + nact - 1) * 128;
        const uint32_t dbase = tmem_base + (uint32_t)((nact - 1) & 1) * 128;
        const int sub = wid & 3;
        const int row = prow0 + sub * 32 + lane;
        const int nch = (wid < 4) ? 2 : 1;
        const int cst = (wid < 4) ? 0 : 64;
        for (int ch = 0; ch < nch; ch++) {
            int c0 = cst + ch * 32;
            uint32_t d[32];
            TCGEN05_LD_32X32B_X32(d, dbase + c0);
            TCGEN05_WAIT_LD();
            if (row < nrows) {
                float4* op = (float4*)(M + (size_t)row * C + c0);
#pragma unroll
                for (int i = 0; i < 8; i++) {
                    float4 v;
                    v.x = __uint_as_float(d[4 * i + 0]);
                    v.y = __uint_as_float(d[4 * i + 1]);
                    v.z = __uint_as_float(d[4 * i + 2]);
                    v.w = __uint_as_float(d[4 * i + 3]);
                    op[i] = v;
                }
            }
        }
    }

    __syncthreads();
    if (wid == 0) {
        TCGEN05_DEALLOC(tmem_base, 256);
    }
#else
    for (int it = 0; it < nact; it++) {
        int row0 = (tile0 + it) * 128;
        for (int idx = t; idx < 128 * 96; idx += 256) {
            int r = idx / 96, c = idx - r * 96;
            int gr = row0 + r;
            if (gr < nrows) {
                float s = 0.f;
                for (int k = 0; k < 96; k++) s = fmaf(X[gr * 96 + k], Wfb[k * 96 + c], s);
                M[(size_t)gr * C + c] = s;
            }
        }
    }
#endif
}

// ============================================================
// Gates GEMM: pipelined 8-tile blocks; grid (ceil(nt/8), 6).
// y&1 -> gi/gh, y>>1 -> N-third h.
// ============================================================
__global__ void __launch_bounds__(256, 2) gates_mma_kernel(
    const float* __restrict__ A0, const float* __restrict__ A1,
    const float* __restrict__ bias0, const float* __restrict__ bias1,
    float* __restrict__ O0, float* __restrict__ O1, int nrows)
{
    extern __shared__ char smem[];
    const int t = threadIdx.x;
    const int y = blockIdx.y & 1;
    const int h = blockIdx.y >> 1;             // gate cols [96h, 96h+96)

    const float* A    = y ? A1 : A0;
    const float* bias = y ? bias1 : bias0;
    float*       O    = y ? O1 : O0;

    const int ntiles = (nrows + 127) >> 7;
    const int tile0  = blockIdx.x * GATES_TILES;
    int nact = ntiles - tile0;
    if (nact <= 0) return;
    if (nact > GATES_TILES) nact = GATES_TILES;

#if TC_OK
    const uint32_t smem_base = smem_to_u32(smem);
    const int wid  = t >> 5;
    const int lane = t & 31;

    if (wid == 0) {
        TCGEN05_ALLOC(smem_base, 256);       // 2 x 128-col D ping-pong
        TCGEN05_RELINQUISH();
    }
    if (t == 0) MBARRIER_INIT(smem_base + 8, 1);

    // B: copy 96-row slice of the W image (once per block)
    {
        const uint4* src = (const uint4*)(g_wimg[y]);
        uint4* dsth = (uint4*)(smem + XW_BHI);
        uint4* dstl = (uint4*)(smem + XW_BLO);
        const int b0 = (12 * h) * 64;
        const int b1 = (36 + 12 * h) * 64;
#pragma unroll
        for (int i = 0; i < 3; i++) {
            int o = t + i * 256;
            dsth[o]        = src[b0 + o];
            dsth[768 + o]  = src[b1 + o];
            dstl[o]        = src[4608 + b0 + o];
            dstl[768 + o]  = src[4608 + b1 + o];
        }
    }

    __syncthreads();
    uint32_t tmem_base;
    asm volatile("ld.shared.b32 %0, [%1];" : "=r"(tmem_base) : "r"(smem_base));

    const float4* b4 = (const float4*)bias;

    for (int it = 0; it < nact; it++) {
        const int row0 = (tile0 + it) * 128;

        if (it > 0) {
            MBARRIER_WAIT_PARITY(smem_base + 8, (it - 1) & 1);
            TCGEN05_FENCE_AFTER();
        }

        convert_A_tile(A, row0, nrows, smem, t);
        FENCE_PROXY_ASYNC();
        __syncthreads();

        if (wid == 0) {
            TCGEN05_FENCE_AFTER();
            if (elect_one_pred())
                issue_mma_96(smem_base, tmem_base + (uint32_t)(it & 1) * 128,
                             smem_base + 8);
        }

        if (it > 0) {
            const int prow0 = (tile0 + it - 1) * 128;
            const uint32_t dbase = tmem_base + (uint32_t)((it - 1) & 1) * 128;
            const int sub = wid & 3;
            const int row = prow0 + sub * 32 + lane;
            const int nch = (wid < 4) ? 2 : 1;
            const int cst = (wid < 4) ? 0 : 64;
            for (int ch = 0; ch < nch; ch++) {
                int c0 = cst + ch * 32;
                uint32_t d[32];
                TCGEN05_LD_32X32B_X32(d, dbase + c0);
                TCGEN05_WAIT_LD();
                if (row < nrows) {
                    int gc = h * 96 + c0;
                    float4* op = (float4*)(O + (size_t)row * GATE + gc);
#pragma unroll
                    for (int i = 0; i < 8; i++) {
                        float4 bb = __ldg(&b4[gc / 4 + i]);
                        float4 v;
                        v.x = __uint_as_float(d[4 * i + 0]) + bb.x;
                        v.y = __uint_as_float(d[4 * i + 1]) + bb.y;
                        v.z = __uint_as_float(d[4 * i + 2]) + bb.z;
                        v.w = __uint_as_float(d[4 * i + 3]) + bb.w;
                        op[i] = v;
                    }
                }
            }
        }
    }

    // final tile epilogue
    MBARRIER_WAIT_PARITY(smem_base + 8, (nact - 1) & 1);
    TCGEN05_FENCE_AFTER();
    {
        const int prow0 = (tile0 + nact - 1) * 128;
        const uint32_t dbase = tmem_base + (uint32_t)((nact - 1) & 1) * 128;
        const int sub = wid & 3;
        const int row = prow0 + sub * 32 + lane;
        const int nch = (wid < 4) ? 2 : 1;
        const int cst = (wid < 4) ? 0 : 64;
        for (int ch = 0; ch < nch; ch++) {
            int c0 = cst + ch * 32;
            uint32_t d[32];
            TCGEN05_LD_32X32B_X32(d, dbase + c0);
            TCGEN05_WAIT_LD();
            if (row < nrows) {
                int gc = h * 96 + c0;
                float4* op = (float4*)(O + (size_t)row * GATE + gc);
#pragma unroll
                for (int i = 0; i < 8; i++) {
                    float4 bb = __ldg(&b4[gc / 4 + i]);
                    float4 v;
                    v.x = __uint_as_float(d[4 * i + 0]) + bb.x;
                    v.y = __uint_as_float(d[4 * i + 1]) + bb.y;
                    v.z = __uint_as_float(d[4 * i + 2]) + bb.z;
                    v.w = __uint_as_float(d[4 * i + 3]) + bb.w;
                    op[i] = v;
                }
            }
        }
    }

    __syncthreads();
    if (wid == 0) {
        TCGEN05_DEALLOC(tmem_base, 256);
    }
#else
    // SIMT fallback (never runs on HW)
    for (int it = 0; it < nact; it++) {
        int row0 = (tile0 + it) * 128;
        for (int idx = t; idx < 128 * 96; idx += 256) {
            int r = idx / 96, cl = idx - r * 96;
            int c = h * 96 + cl;
            int gr = row0 + r;
            if (gr < nrows) {
                float s = bias[c];
                for (int k = 0; k < 96; k++) {
                    uint32_t byte_off = (uint32_t)(((c >> 3) + (k >> 6) * 36) * 1024
                                                   + (c & 7) * 128 + (k & 63) * 2);
                    uint32_t slot = SMEM_SWIZZLE_128B(byte_off & ~3u) >> 2;
                    uint32_t hv = g_wimg[y][slot];
                    uint32_t lv = g_wimg[y][slot + 18432];
                    int sh = (k & 1) ? 16 : 0;
                    float wh = __bfloat162float(__ushort_as_bfloat16((unsigned short)(hv >> sh)));
                    float wl = __bfloat162float(__ushort_as_bfloat16((unsigned short)(lv >> sh)));
                    s = fmaf(A[gr * 96 + k], wh + wl, s);
                }
                O[(size_t)gr * GATE + c] = s;
            }
        }
    }
#endif
}

// ============================================================
// GRU elementwise
// ============================================================
__device__ __forceinline__ float gru_one(float ir, float iz, float inn,
                                         float hr, float hz, float hn, float h)
{
    float r = 1.f / (1.f + expf(-(ir + hr)));
    float z = 1.f / (1.f + expf(-(iz + hz)));
    float n = tanhf(inn + r * hn);
    return (1.f - z) * n + z * h;
}

__global__ void gru_kernel(const float* __restrict__ GI,
                           const float* __restrict__ GH,
                           const float* __restrict__ H,
                           float* __restrict__ OUT,
                           int nrows)
{
    int tid = blockIdx.x * blockDim.x + threadIdx.x;
    int total = nrows * 24;
    if (tid >= total) return;
    int n = tid / 24;
    int q = tid - n * 24;

    const float4* gi4 = (const float4*)GI;
    const float4* gh4 = (const float4*)GH;
    float4 ir  = gi4[n * 72 + q];
    float4 iz  = gi4[n * 72 + 24 + q];
    float4 inn = gi4[n * 72 + 48 + q];
    float4 hr  = gh4[n * 72 + q];
    float4 hz  = gh4[n * 72 + 24 + q];
    float4 hn  = gh4[n * 72 + 48 + q];
    float4 h   = ((const float4*)H)[n * 24 + q];

    float4 o;
    o.x = gru_one(ir.x, iz.x, inn.x, hr.x, hz.x, hn.x, h.x);
    o.y = gru_one(ir.y, iz.y, inn.y, hr.y, hz.y, hn.y, h.y);
    o.z = gru_one(ir.z, iz.z, inn.z, hr.z, hz.z, hn.z, h.z);
    o.w = gru_one(ir.w, iz.w, inn.w, hr.w, hz.w, hn.w, h.w);

    ((float4*)OUT)[n * 24 + q] = o;
}

// ============================================================
extern "C" void kernel_launch(void* const* d_in, const int* in_sizes, int n_in,
                              void* d_out, int out_size)
{
    const float* x      = (const float*)d_in[0];
    const int*   ei     = (const int*)  d_in[1];
    const float* weight = (const float*)d_in[2];
    const float* w_ih   = (const float*)d_in[3];
    const float* w_hh   = (const float*)d_in[4];
    const float* b_ih   = (const float*)d_in[5];
    const float* b_hh   = (const float*)d_in[6];
    float* out = (float*)d_out;

    const int nrows  = in_sizes[0] / C;
    const int nedges = in_sizes[1] / 2;

    float *pm, *pagg, *pgi, *pgh, *px1, *px2;
    uint32_t* pwx;
    cudaGetSymbolAddress((void**)&pm,   g_m);
    cudaGetSymbolAddress((void**)&pagg, g_agg);
    cudaGetSymbolAddress((void**)&pgi,  g_gi);
    cudaGetSymbolAddress((void**)&pgh,  g_gh);
    cudaGetSymbolAddress((void**)&px1,  g_x1);
    cudaGetSymbolAddress((void**)&px2,  g_x2);
    cudaGetSymbolAddress((void**)&pwx,  g_wximg);

    cudaFuncSetAttribute(xw_mma_kernel,    cudaFuncAttributeMaxDynamicSharedMemorySize, XW_TOTAL);
    cudaFuncSetAttribute(gates_mma_kernel, cudaFuncAttributeMaxDynamicSharedMemorySize, XW_TOTAL);

    const int rblocks128 = (nrows + 127) / 128;
    const int gblocks    = (rblocks128 + GATES_TILES - 1) / GATES_TILES;
    const int xblocks    = (rblocks128 + XW_TILES - 1) / XW_TILES;
    dim3 g_gates(gblocks, 6);
    const int gru_blocks = (nrows * 24 + 255) / 256;
    const int agg_blocks = (nrows * 32 + 255) / 256;
    const int nb256      = (nrows + 255) / 256;

    // Precompute: W images + CSR (layer-invariant)
    conv_w_kernel<<<(2 * 288 * 64 + 255) / 256, 256>>>(w_ih, w_hh);
    conv_wx_kernel<<<(3 * 96 * 64 + 255) / 256, 256>>>(weight);
    csr_zero_kernel<<<nb256, 256>>>(nrows);
    csr_count_kernel<<<(nedges + 255) / 256, 256>>>(ei, nedges);
    scan1_kernel<<<nb256, 256>>>(nrows);
    scan2_kernel<<<1, 256>>>(nb256, nrows);
    scan3_kernel<<<nb256, 256>>>(nrows);
    csr_fill_kernel<<<(nedges + 255) / 256, 256>>>(ei, nedges);

    const float* xin = x;
    float* xbufs[3] = {px1, px2, out};

    for (int l = 0; l < 3; l++) {
        float* xout = xbufs[l];
        xw_mma_kernel<<<xblocks, 256, XW_TOTAL>>>(pwx + l * 12288, xin,
                                                  weight + l * C * C, pm, nrows);
        agg_kernel<<<agg_blocks, 256>>>(pm, pagg, nrows);
        gates_mma_kernel<<<g_gates, 256, XW_TOTAL>>>(pagg, xin, b_ih, b_hh,
                                                     pgi, pgh, nrows);
        gru_kernel<<<gru_blocks, 256>>>(pgi, pgh, xin, xout, nrows);
        xin = xout;
    }
}